// round 1
// baseline (speedup 1.0000x reference)
#include <cuda_runtime.h>
#include <cstdint>

#define BB 8
#define CC 128
#define FF 16
#define NN 512
#define GG 3
#define ZCAP 4096
#define ROWP 132   // padded row stride (floats): 132*4=528 bytes, 16B-aligned rows

// -------- device scratch (no allocation allowed) --------
__device__ float g_T1[BB*FF*CC];          // [bf][c]  sum_u X[u,c]*S[u,c]
__device__ float g_T2[BB*FF*CC];          // [bf][c]  sum_u X[u,c]
__device__ float g_k0[BB*FF*CC];          // [bf][o]  Wn @ (T1 + T2*bd)
__device__ float g_Q [BB*FF*CC*CC];       // [bf][o][e]  (Wn . T2) @ WD
__device__ int   g_znum[BB*GG];
__device__ int   g_zcnt[BB*GG*NN];
__device__ int2  g_zlist[BB*GG*ZCAP];

typedef unsigned long long u64;

__device__ __forceinline__ u64 pk2(float lo, float hi){
    u64 r; asm("mov.b64 %0,{%1,%2};" : "=l"(r) : "f"(lo), "f"(hi)); return r;
}
__device__ __forceinline__ u64 dup2(float x){ return pk2(x, x); }
__device__ __forceinline__ void unpk2(u64 v, float& a, float& b){
    asm("mov.b64 {%0,%1},%2;" : "=f"(a), "=f"(b) : "l"(v));
}
__device__ __forceinline__ void fma2(u64& acc, u64 a, u64 b){
    asm("fma.rn.f32x2 %0,%1,%2,%0;" : "+l"(acc) : "l"(a), "l"(b));
}

// -------- init: zero the zero-tracking state --------
__global__ void kinit(){
    int t = blockIdx.x*blockDim.x + threadIdx.x;
    if (t < BB*GG) g_znum[t] = 0;
    for (int i = t; i < BB*GG*NN; i += gridDim.x*blockDim.x) g_zcnt[i] = 0;
}

// -------- scan Y slices 0..2 for exact zeros --------
__global__ void kscan(const float* __restrict__ Y){
    int gtid = blockIdx.x*blockDim.x + threadIdx.x;       // 1,572,864 threads
    int bg   = gtid >> 16;                                 // 0..23
    int off4 = gtid & 65535;
    int b = bg / GG, g = bg % GG;
    const float4 y4 = reinterpret_cast<const float4*>(Y)[(size_t)(b*FF + g)*65536 + off4];
    int l = off4 * 4;
    int u = l >> 9, v = l & 511;
    float vals[4] = {y4.x, y4.y, y4.z, y4.w};
    #pragma unroll
    for (int r = 0; r < 4; ++r){
        if (vals[r] == 0.0f){
            int pos = atomicAdd(&g_znum[bg], 1);
            if (pos < ZCAP) g_zlist[bg*ZCAP + pos] = make_int2(u, v + r);
            atomicAdd(&g_zcnt[bg*NN + v + r], 1);
        }
    }
}

// -------- K1: per (b,f) compute T1[c], T2[c] via S = X @ WS^T --------
__global__ void k1_T(const float* __restrict__ infos, const float* __restrict__ Wd){
    extern __shared__ float sm[];
    float* sW = sm;                  // WS stored [c][d], row stride ROWP
    float* sX = sm + 128*ROWP;       // X  stored [c][u], row stride ROWP
    __shared__ float sRed[16*128];

    int bf = blockIdx.x; int b = bf >> 4; int f = bf & 15;
    int t  = threadIdx.x; int ty = t >> 4, tx = t & 15;

    // WS[d][c] = Wd[d*384+c] + Wd[d*384+256+c]; store transposed sW[c][d]
    for (int k = t; k < 128*128; k += 256){
        int d = k >> 7, c = k & 127;
        sW[c*ROWP + d] = Wd[d*384 + c] + Wd[d*384 + 256 + c];
    }

    const size_t base = (size_t)(b*2048 + f) * 512;   // + c*8192 + u
    float t1p[8] = {0,0,0,0,0,0,0,0};
    float t2p[8] = {0,0,0,0,0,0,0,0};

    for (int ut = 0; ut < 4; ++ut){
        int u0 = ut * 128;
        __syncthreads();
        for (int k = t; k < 128*32; k += 256){
            int c = k >> 5, q = k & 31;
            float4 x4 = *reinterpret_cast<const float4*>(infos + base + (size_t)c*8192 + u0 + q*4);
            *reinterpret_cast<float4*>(&sX[c*ROWP + q*4]) = x4;
        }
        __syncthreads();

        u64 acc[4][8];
        #pragma unroll
        for (int p = 0; p < 4; ++p)
            #pragma unroll
            for (int j = 0; j < 8; ++j) acc[p][j] = 0ull;

        #pragma unroll 2
        for (int c = 0; c < 128; ++c){
            float4 xa0 = *reinterpret_cast<float4*>(&sX[c*ROWP + ty*8]);
            float4 xa1 = *reinterpret_cast<float4*>(&sX[c*ROWP + ty*8 + 4]);
            float4 w0  = *reinterpret_cast<float4*>(&sW[c*ROWP + tx*8]);
            float4 w1  = *reinterpret_cast<float4*>(&sW[c*ROWP + tx*8 + 4]);
            u64 xp[4] = {pk2(xa0.x,xa0.y), pk2(xa0.z,xa0.w), pk2(xa1.x,xa1.y), pk2(xa1.z,xa1.w)};
            u64 wq[8] = {dup2(w0.x),dup2(w0.y),dup2(w0.z),dup2(w0.w),
                         dup2(w1.x),dup2(w1.y),dup2(w1.z),dup2(w1.w)};
            #pragma unroll
            for (int j = 0; j < 8; ++j)
                #pragma unroll
                for (int p = 0; p < 4; ++p) fma2(acc[p][j], xp[p], wq[j]);
        }

        // accumulate T1/T2 partials: X[u,d] = sX[d][u] (d is this thread's output col)
        #pragma unroll
        for (int j = 0; j < 8; ++j){
            int d = tx*8 + j;
            #pragma unroll
            for (int p = 0; p < 4; ++p){
                float s0, s1; unpk2(acc[p][j], s0, s1);
                float x0 = sX[d*ROWP + ty*8 + 2*p];
                float x1 = sX[d*ROWP + ty*8 + 2*p + 1];
                t1p[j] += x0*s0 + x1*s1;
                t2p[j] += x0 + x1;
            }
        }
    }

    // block reduction over ty (u-rows) for each d
    __syncthreads();
    #pragma unroll
    for (int j = 0; j < 8; ++j) sRed[ty*128 + tx*8 + j] = t1p[j];
    __syncthreads();
    if (t < 128){
        float s = 0;
        #pragma unroll
        for (int yy = 0; yy < 16; ++yy) s += sRed[yy*128 + t];
        g_T1[bf*128 + t] = s;
    }
    __syncthreads();
    #pragma unroll
    for (int j = 0; j < 8; ++j) sRed[ty*128 + tx*8 + j] = t2p[j];
    __syncthreads();
    if (t < 128){
        float s = 0;
        #pragma unroll
        for (int yy = 0; yy < 16; ++yy) s += sRed[yy*128 + t];
        g_T2[bf*128 + t] = s;
    }
}

// -------- K2: per (b,f) Q[o,e] = sum_c Wn[o,c]*T2[c]*WD[c,e]; k0[o] --------
__global__ void k2_Q(const float* __restrict__ Wd, const float* __restrict__ Wn,
                     const float* __restrict__ bd){
    extern __shared__ float sm[];
    float* sC = sm;                  // Wn transposed: sC[c][o]
    float* sB = sm + 128*ROWP;       // T2[c]*WD[c,e]: sB[c][e]
    __shared__ float sVec[128];

    int bf = blockIdx.x;
    int t  = threadIdx.x; int ty = t >> 4, tx = t & 15;

    for (int k = t; k < 128*128; k += 256){
        int o = k >> 7, c = k & 127;
        sC[c*ROWP + o] = Wn[o*128 + c];
    }
    for (int k = t; k < 128*128; k += 256){
        int c = k >> 7, e = k & 127;
        float wdv = Wd[c*384 + 128 + e] - Wd[c*384 + 256 + e];
        sB[c*ROWP + e] = g_T2[bf*128 + c] * wdv;
    }
    if (t < 128) sVec[t] = g_T1[bf*128 + t] + g_T2[bf*128 + t] * bd[t];
    __syncthreads();

    u64 acc[8][4];
    #pragma unroll
    for (int i = 0; i < 8; ++i)
        #pragma unroll
        for (int p = 0; p < 4; ++p) acc[i][p] = 0ull;

    #pragma unroll 2
    for (int c = 0; c < 128; ++c){
        float4 a0 = *reinterpret_cast<float4*>(&sC[c*ROWP + ty*8]);
        float4 a1 = *reinterpret_cast<float4*>(&sC[c*ROWP + ty*8 + 4]);
        float4 b0 = *reinterpret_cast<float4*>(&sB[c*ROWP + tx*8]);
        float4 b1 = *reinterpret_cast<float4*>(&sB[c*ROWP + tx*8 + 4]);
        u64 bp[4] = {pk2(b0.x,b0.y), pk2(b0.z,b0.w), pk2(b1.x,b1.y), pk2(b1.z,b1.w)};
        float av[8] = {a0.x,a0.y,a0.z,a0.w,a1.x,a1.y,a1.z,a1.w};
        #pragma unroll
        for (int i = 0; i < 8; ++i){
            u64 da = dup2(av[i]);
            #pragma unroll
            for (int p = 0; p < 4; ++p) fma2(acc[i][p], da, bp[p]);
        }
    }

    // write Q[o][e]
    #pragma unroll
    for (int i = 0; i < 8; ++i){
        int o = ty*8 + i;
        float v[8];
        #pragma unroll
        for (int p = 0; p < 4; ++p) unpk2(acc[i][p], v[2*p], v[2*p+1]);
        float4* dst = reinterpret_cast<float4*>(&g_Q[((size_t)bf*128 + o)*128 + tx*8]);
        dst[0] = make_float4(v[0],v[1],v[2],v[3]);
        dst[1] = make_float4(v[4],v[5],v[6],v[7]);
    }

    // k0[o] = sum_c Wn[o,c]*sVec[c]
    if (t < 128){
        float s = 0;
        for (int c = 0; c < 128; ++c) s += sC[c*ROWP + t] * sVec[c];
        g_k0[bf*128 + t] = s;
    }
}

// -------- K3: out[b,o,f,v] = relu((k0[o] + X[v]@Q[o]) / 512 + bn[o]) --------
__global__ void k3_out(const float* __restrict__ infos, const float* __restrict__ bn,
                       float* __restrict__ out){
    extern __shared__ float sm[];
    float* sXv = sm;                 // [e][v]
    float* sQ  = sm + 128*ROWP;      // [e][o]

    int bid = blockIdx.x;
    int bf = bid >> 2; int vt = bid & 3; int v0 = vt*128;
    int b = bf >> 4; int f = bf & 15;
    int t = threadIdx.x; int ty = t >> 4, tx = t & 15;

    const size_t base = (size_t)(b*2048 + f) * 512;
    for (int k = t; k < 128*32; k += 256){
        int e = k >> 5, q = k & 31;
        float4 x4 = *reinterpret_cast<const float4*>(infos + base + (size_t)e*8192 + v0 + q*4);
        *reinterpret_cast<float4*>(&sXv[e*ROWP + q*4]) = x4;
    }
    for (int k = t; k < 128*32; k += 256){
        int o = k >> 5, q = k & 31;
        float4 qv = *reinterpret_cast<const float4*>(&g_Q[((size_t)bf*128 + o)*128 + q*4]);
        sQ[(q*4+0)*ROWP + o] = qv.x;
        sQ[(q*4+1)*ROWP + o] = qv.y;
        sQ[(q*4+2)*ROWP + o] = qv.z;
        sQ[(q*4+3)*ROWP + o] = qv.w;
    }
    __syncthreads();

    u64 acc[4][8];   // o-pair p, v-slot j (v = tx + 16*j)
    #pragma unroll
    for (int p = 0; p < 4; ++p)
        #pragma unroll
        for (int j = 0; j < 8; ++j) acc[p][j] = 0ull;

    #pragma unroll 2
    for (int e = 0; e < 128; ++e){
        float4 q0 = *reinterpret_cast<float4*>(&sQ[e*ROWP + ty*8]);
        float4 q1 = *reinterpret_cast<float4*>(&sQ[e*ROWP + ty*8 + 4]);
        u64 qp[4] = {pk2(q0.x,q0.y), pk2(q0.z,q0.w), pk2(q1.x,q1.y), pk2(q1.z,q1.w)};
        #pragma unroll
        for (int j = 0; j < 8; ++j){
            u64 dx = dup2(sXv[e*ROWP + tx + 16*j]);
            #pragma unroll
            for (int p = 0; p < 4; ++p) fma2(acc[p][j], qp[p], dx);
        }
    }

    float k0v[8], bnv[8];
    #pragma unroll
    for (int i = 0; i < 8; ++i){
        k0v[i] = g_k0[bf*128 + ty*8 + i];
        bnv[i] = bn[ty*8 + i];
    }
    const float inv = 1.0f / 512.0f;
    #pragma unroll
    for (int p = 0; p < 4; ++p){
        int o0 = ty*8 + 2*p;
        #pragma unroll
        for (int j = 0; j < 8; ++j){
            float s0, s1; unpk2(acc[p][j], s0, s1);
            float r0 = fmaxf((k0v[2*p]   + s0)*inv + bnv[2*p],   0.0f);
            float r1 = fmaxf((k0v[2*p+1] + s1)*inv + bnv[2*p+1], 0.0f);
            int v = v0 + tx + 16*j;
            out[(size_t)(b*2048 + o0*16     + f)*512 + v] = r0;
            out[(size_t)(b*2048 + (o0+1)*16 + f)*512 + v] = r1;
        }
    }
}

// -------- K4: exact recompute of the rare zero-affected output columns --------
__global__ void k4_fix(const float* __restrict__ infos, const float* __restrict__ Wd,
                       const float* __restrict__ bd, const float* __restrict__ Wn,
                       const float* __restrict__ bn, float* __restrict__ out){
    int slot = blockIdx.x;           // 0..15
    int bf   = blockIdx.y;
    int b = bf >> 4, f = bf & 15;
    int g = (f == 0) ? 0 : ((f <= 11) ? 1 : 2);
    int bg = b*GG + g;
    int nz = g_znum[bg]; if (nz > ZCAP) nz = ZCAP;
    int t = threadIdx.x;             // 128 threads

    __shared__ float sXv[128];
    __shared__ float sXu[16][128];
    __shared__ float sAgg[128];
    __shared__ int   sUs[16];
    __shared__ int   sM;

    for (int i = slot; i < nz; i += 16){
        int vz = g_zlist[bg*ZCAP + i].y;
        bool dup = false;
        for (int jj = 0; jj < i; ++jj)
            if (g_zlist[bg*ZCAP + jj].y == vz){ dup = true; break; }
        if (dup) continue;

        if (t == 0){
            int m = 0;
            for (int jj = 0; jj < nz; ++jj){
                int2 e = g_zlist[bg*ZCAP + jj];
                if (e.y == vz && m < 16) sUs[m++] = e.x;
            }
            sM = m;
        }
        __syncthreads();
        int m = sM;

        sXv[t] = infos[(size_t)(b*2048 + t*16 + f)*512 + vz];
        for (int k = 0; k < m; ++k)
            sXu[k][t] = infos[(size_t)(b*2048 + t*16 + f)*512 + sUs[k]];
        __syncthreads();

        int c = t;
        float Dv = 0.0f;
        for (int e = 0; e < 128; ++e)
            Dv += sXv[e] * (Wd[c*384 + 128 + e] - Wd[c*384 + 256 + e]);
        float a1 = g_T1[bf*128 + c];
        float a2 = g_T2[bf*128 + c];
        for (int k = 0; k < m; ++k){
            float S = 0.0f;
            for (int e = 0; e < 128; ++e)
                S += sXu[k][e] * (Wd[c*384 + e] + Wd[c*384 + 256 + e]);
            a1 -= sXu[k][c] * S;
            a2 -= sXu[k][c];
        }
        int degi = 512 - g_zcnt[bg*NN + vz];
        float deg = (float)(degi > 1 ? degi : 1);
        sAgg[c] = (a1 + a2*(Dv + bd[c])) / deg;
        __syncthreads();

        float s = 0.0f;
        for (int cc = 0; cc < 128; ++cc) s += sAgg[cc] * Wn[t*128 + cc];
        s += bn[t];
        out[(size_t)(b*2048 + t*16 + f)*512 + vz] = fmaxf(s, 0.0f);
        __syncthreads();
    }
}

extern "C" void kernel_launch(void* const* d_in, const int* in_sizes, int n_in,
                              void* d_out, int out_size){
    const float* Y     = (const float*)d_in[0];
    const float* infos = (const float*)d_in[1];
    const float* Wd    = (const float*)d_in[2];
    const float* bd    = (const float*)d_in[3];
    const float* Wn    = (const float*)d_in[4];
    const float* bn    = (const float*)d_in[5];
    float* out = (float*)d_out;

    const int dynsm = 2 * 128 * ROWP * 4;   // 135168 bytes
    cudaFuncSetAttribute(k1_T,  cudaFuncAttributeMaxDynamicSharedMemorySize, dynsm);
    cudaFuncSetAttribute(k2_Q,  cudaFuncAttributeMaxDynamicSharedMemorySize, dynsm);
    cudaFuncSetAttribute(k3_out,cudaFuncAttributeMaxDynamicSharedMemorySize, dynsm);

    kinit<<<16, 256>>>();
    kscan<<<6144, 256>>>(Y);
    k1_T<<<128, 256, dynsm>>>(infos, Wd);
    k2_Q<<<128, 256, dynsm>>>(Wd, Wn, bd);
    k3_out<<<512, 256, dynsm>>>(infos, bn, out);
    k4_fix<<<dim3(16, 128), 128>>>(infos, Wd, bd, Wn, bn, out);
}

// round 2
// speedup vs baseline: 1.0005x; 1.0005x over previous
#include <cuda_runtime.h>
#include <cstdint>

#define BB 8
#define CC 128
#define FF 16
#define NN 512
#define GG 3
#define ZCAP 4096
#define ROWP 132   // padded row stride (floats): 132*4=528 bytes, 16B-aligned rows

// -------- device scratch (no allocation allowed) --------
__device__ float g_T1[BB*FF*CC];          // [bf][c]  sum_u X[u,c]*S[u,c]
__device__ float g_T2[BB*FF*CC];          // [bf][c]  sum_u X[u,c]
__device__ float g_k0[BB*FF*CC];          // [bf][o]  Wn @ (T1 + T2*bd)
__device__ float g_Q [BB*FF*CC*CC];       // [bf][o][e]  (Wn . T2) @ WD
__device__ int   g_znum[BB*GG];
__device__ int   g_zcnt[BB*GG*NN];
__device__ int2  g_zlist[BB*GG*ZCAP];

typedef unsigned long long u64;

__device__ __forceinline__ u64 pk2(float lo, float hi){
    u64 r; asm("mov.b64 %0,{%1,%2};" : "=l"(r) : "f"(lo), "f"(hi)); return r;
}
__device__ __forceinline__ u64 dup2(float x){ return pk2(x, x); }
__device__ __forceinline__ void unpk2(u64 v, float& a, float& b){
    asm("mov.b64 {%0,%1},%2;" : "=f"(a), "=f"(b) : "l"(v));
}
__device__ __forceinline__ void fma2(u64& acc, u64 a, u64 b){
    asm("fma.rn.f32x2 %0,%1,%2,%0;" : "+l"(acc) : "l"(a), "l"(b));
}

// -------- init: zero the zero-tracking state --------
__global__ void kinit(){
    int t = blockIdx.x*blockDim.x + threadIdx.x;
    if (t < BB*GG) g_znum[t] = 0;
    for (int i = t; i < BB*GG*NN; i += gridDim.x*blockDim.x) g_zcnt[i] = 0;
}

// -------- scan Y slices 0..2 for exact zeros --------
__global__ void kscan(const float* __restrict__ Y){
    int gtid = blockIdx.x*blockDim.x + threadIdx.x;       // 1,572,864 threads
    int bg   = gtid >> 16;                                 // 0..23
    int off4 = gtid & 65535;
    int b = bg / GG, g = bg % GG;
    const float4 y4 = reinterpret_cast<const float4*>(Y)[(size_t)(b*FF + g)*65536 + off4];
    int l = off4 * 4;
    int u = l >> 9, v = l & 511;
    float vals[4] = {y4.x, y4.y, y4.z, y4.w};
    #pragma unroll
    for (int r = 0; r < 4; ++r){
        if (vals[r] == 0.0f){
            int pos = atomicAdd(&g_znum[bg], 1);
            if (pos < ZCAP) g_zlist[bg*ZCAP + pos] = make_int2(u, v + r);
            atomicAdd(&g_zcnt[bg*NN + v + r], 1);
        }
    }
}

// -------- K1: per (b,f) compute T1[c], T2[c] via S = X @ WS^T --------
__global__ void k1_T(const float* __restrict__ infos, const float* __restrict__ Wd){
    extern __shared__ float sm[];
    float* sW = sm;                  // WS stored [c][d], row stride ROWP
    float* sX = sm + 128*ROWP;       // X  stored [c][u], row stride ROWP
    __shared__ float sRed[16*128];

    int bf = blockIdx.x; int b = bf >> 4; int f = bf & 15;
    int t  = threadIdx.x; int ty = t >> 4, tx = t & 15;

    // WS[d][c] = Wd[d*384+c] + Wd[d*384+256+c]; store transposed sW[c][d]
    for (int k = t; k < 128*128; k += 256){
        int d = k >> 7, c = k & 127;
        sW[c*ROWP + d] = Wd[d*384 + c] + Wd[d*384 + 256 + c];
    }

    const size_t base = (size_t)(b*2048 + f) * 512;   // + c*8192 + u
    float t1p[8] = {0,0,0,0,0,0,0,0};
    float t2p[8] = {0,0,0,0,0,0,0,0};

    for (int ut = 0; ut < 4; ++ut){
        int u0 = ut * 128;
        __syncthreads();
        for (int k = t; k < 128*32; k += 256){
            int c = k >> 5, q = k & 31;
            float4 x4 = *reinterpret_cast<const float4*>(infos + base + (size_t)c*8192 + u0 + q*4);
            *reinterpret_cast<float4*>(&sX[c*ROWP + q*4]) = x4;
        }
        __syncthreads();

        u64 acc[4][8];
        #pragma unroll
        for (int p = 0; p < 4; ++p)
            #pragma unroll
            for (int j = 0; j < 8; ++j) acc[p][j] = 0ull;

        #pragma unroll 2
        for (int c = 0; c < 128; ++c){
            float4 xa0 = *reinterpret_cast<float4*>(&sX[c*ROWP + ty*8]);
            float4 xa1 = *reinterpret_cast<float4*>(&sX[c*ROWP + ty*8 + 4]);
            float4 w0  = *reinterpret_cast<float4*>(&sW[c*ROWP + tx*8]);
            float4 w1  = *reinterpret_cast<float4*>(&sW[c*ROWP + tx*8 + 4]);
            u64 xp[4] = {pk2(xa0.x,xa0.y), pk2(xa0.z,xa0.w), pk2(xa1.x,xa1.y), pk2(xa1.z,xa1.w)};
            u64 wq[8] = {dup2(w0.x),dup2(w0.y),dup2(w0.z),dup2(w0.w),
                         dup2(w1.x),dup2(w1.y),dup2(w1.z),dup2(w1.w)};
            #pragma unroll
            for (int j = 0; j < 8; ++j)
                #pragma unroll
                for (int p = 0; p < 4; ++p) fma2(acc[p][j], xp[p], wq[j]);
        }

        // accumulate T1/T2 partials: X[u,d] = sX[d][u] (d is this thread's output col)
        #pragma unroll
        for (int j = 0; j < 8; ++j){
            int d = tx*8 + j;
            #pragma unroll
            for (int p = 0; p < 4; ++p){
                float s0, s1; unpk2(acc[p][j], s0, s1);
                float x0 = sX[d*ROWP + ty*8 + 2*p];
                float x1 = sX[d*ROWP + ty*8 + 2*p + 1];
                t1p[j] += x0*s0 + x1*s1;
                t2p[j] += x0 + x1;
            }
        }
    }

    // block reduction over ty (u-rows) for each d
    __syncthreads();
    #pragma unroll
    for (int j = 0; j < 8; ++j) sRed[ty*128 + tx*8 + j] = t1p[j];
    __syncthreads();
    if (t < 128){
        float s = 0;
        #pragma unroll
        for (int yy = 0; yy < 16; ++yy) s += sRed[yy*128 + t];
        g_T1[bf*128 + t] = s;
    }
    __syncthreads();
    #pragma unroll
    for (int j = 0; j < 8; ++j) sRed[ty*128 + tx*8 + j] = t2p[j];
    __syncthreads();
    if (t < 128){
        float s = 0;
        #pragma unroll
        for (int yy = 0; yy < 16; ++yy) s += sRed[yy*128 + t];
        g_T2[bf*128 + t] = s;
    }
}

// -------- K2: per (b,f) Q[o,e] = sum_c Wn[o,c]*T2[c]*WD[c,e]; k0[o] --------
__global__ void k2_Q(const float* __restrict__ Wd, const float* __restrict__ Wn,
                     const float* __restrict__ bd){
    extern __shared__ float sm[];
    float* sC = sm;                  // Wn transposed: sC[c][o]
    float* sB = sm + 128*ROWP;       // T2[c]*WD[c,e]: sB[c][e]
    __shared__ float sVec[128];

    int bf = blockIdx.x;
    int t  = threadIdx.x; int ty = t >> 4, tx = t & 15;

    for (int k = t; k < 128*128; k += 256){
        int o = k >> 7, c = k & 127;
        sC[c*ROWP + o] = Wn[o*128 + c];
    }
    for (int k = t; k < 128*128; k += 256){
        int c = k >> 7, e = k & 127;
        float wdv = Wd[c*384 + 128 + e] - Wd[c*384 + 256 + e];
        sB[c*ROWP + e] = g_T2[bf*128 + c] * wdv;
    }
    if (t < 128) sVec[t] = g_T1[bf*128 + t] + g_T2[bf*128 + t] * bd[t];
    __syncthreads();

    u64 acc[8][4];
    #pragma unroll
    for (int i = 0; i < 8; ++i)
        #pragma unroll
        for (int p = 0; p < 4; ++p) acc[i][p] = 0ull;

    #pragma unroll 2
    for (int c = 0; c < 128; ++c){
        float4 a0 = *reinterpret_cast<float4*>(&sC[c*ROWP + ty*8]);
        float4 a1 = *reinterpret_cast<float4*>(&sC[c*ROWP + ty*8 + 4]);
        float4 b0 = *reinterpret_cast<float4*>(&sB[c*ROWP + tx*8]);
        float4 b1 = *reinterpret_cast<float4*>(&sB[c*ROWP + tx*8 + 4]);
        u64 bp[4] = {pk2(b0.x,b0.y), pk2(b0.z,b0.w), pk2(b1.x,b1.y), pk2(b1.z,b1.w)};
        float av[8] = {a0.x,a0.y,a0.z,a0.w,a1.x,a1.y,a1.z,a1.w};
        #pragma unroll
        for (int i = 0; i < 8; ++i){
            u64 da = dup2(av[i]);
            #pragma unroll
            for (int p = 0; p < 4; ++p) fma2(acc[i][p], da, bp[p]);
        }
    }

    // write Q[o][e]
    #pragma unroll
    for (int i = 0; i < 8; ++i){
        int o = ty*8 + i;
        float v[8];
        #pragma unroll
        for (int p = 0; p < 4; ++p) unpk2(acc[i][p], v[2*p], v[2*p+1]);
        float4* dst = reinterpret_cast<float4*>(&g_Q[((size_t)bf*128 + o)*128 + tx*8]);
        dst[0] = make_float4(v[0],v[1],v[2],v[3]);
        dst[1] = make_float4(v[4],v[5],v[6],v[7]);
    }

    // k0[o] = sum_c Wn[o,c]*sVec[c]
    if (t < 128){
        float s = 0;
        for (int c = 0; c < 128; ++c) s += sC[c*ROWP + t] * sVec[c];
        g_k0[bf*128 + t] = s;
    }
}

// -------- K3: out[b,o,f,v] = relu((k0[o] + X[v]@Q[o]) / 512 + bn[o]) --------
__global__ void k3_out(const float* __restrict__ infos, const float* __restrict__ bn,
                       float* __restrict__ out){
    extern __shared__ float sm[];
    float* sXv = sm;                 // [e][v]
    float* sQ  = sm + 128*ROWP;      // [e][o]

    int bid = blockIdx.x;
    int bf = bid >> 2; int vt = bid & 3; int v0 = vt*128;
    int b = bf >> 4; int f = bf & 15;
    int t = threadIdx.x; int ty = t >> 4, tx = t & 15;

    const size_t base = (size_t)(b*2048 + f) * 512;
    for (int k = t; k < 128*32; k += 256){
        int e = k >> 5, q = k & 31;
        float4 x4 = *reinterpret_cast<const float4*>(infos + base + (size_t)e*8192 + v0 + q*4);
        *reinterpret_cast<float4*>(&sXv[e*ROWP + q*4]) = x4;
    }
    for (int k = t; k < 128*32; k += 256){
        int o = k >> 5, q = k & 31;
        float4 qv = *reinterpret_cast<const float4*>(&g_Q[((size_t)bf*128 + o)*128 + q*4]);
        sQ[(q*4+0)*ROWP + o] = qv.x;
        sQ[(q*4+1)*ROWP + o] = qv.y;
        sQ[(q*4+2)*ROWP + o] = qv.z;
        sQ[(q*4+3)*ROWP + o] = qv.w;
    }
    __syncthreads();

    u64 acc[4][8];   // o-pair p, v-slot j (v = tx + 16*j)
    #pragma unroll
    for (int p = 0; p < 4; ++p)
        #pragma unroll
        for (int j = 0; j < 8; ++j) acc[p][j] = 0ull;

    #pragma unroll 2
    for (int e = 0; e < 128; ++e){
        float4 q0 = *reinterpret_cast<float4*>(&sQ[e*ROWP + ty*8]);
        float4 q1 = *reinterpret_cast<float4*>(&sQ[e*ROWP + ty*8 + 4]);
        u64 qp[4] = {pk2(q0.x,q0.y), pk2(q0.z,q0.w), pk2(q1.x,q1.y), pk2(q1.z,q1.w)};
        #pragma unroll
        for (int j = 0; j < 8; ++j){
            u64 dx = dup2(sXv[e*ROWP + tx + 16*j]);
            #pragma unroll
            for (int p = 0; p < 4; ++p) fma2(acc[p][j], qp[p], dx);
        }
    }

    float k0v[8], bnv[8];
    #pragma unroll
    for (int i = 0; i < 8; ++i){
        k0v[i] = g_k0[bf*128 + ty*8 + i];
        bnv[i] = bn[ty*8 + i];
    }
    const float inv = 1.0f / 512.0f;
    #pragma unroll
    for (int p = 0; p < 4; ++p){
        int o0 = ty*8 + 2*p;
        #pragma unroll
        for (int j = 0; j < 8; ++j){
            float s0, s1; unpk2(acc[p][j], s0, s1);
            float r0 = fmaxf((k0v[2*p]   + s0)*inv + bnv[2*p],   0.0f);
            float r1 = fmaxf((k0v[2*p+1] + s1)*inv + bnv[2*p+1], 0.0f);
            int v = v0 + tx + 16*j;
            out[(size_t)(b*2048 + o0*16     + f)*512 + v] = r0;
            out[(size_t)(b*2048 + (o0+1)*16 + f)*512 + v] = r1;
        }
    }
}

// -------- K4: exact recompute of the rare zero-affected output columns --------
__global__ void k4_fix(const float* __restrict__ infos, const float* __restrict__ Wd,
                       const float* __restrict__ bd, const float* __restrict__ Wn,
                       const float* __restrict__ bn, float* __restrict__ out){
    int slot = blockIdx.x;           // 0..15
    int bf   = blockIdx.y;
    int b = bf >> 4, f = bf & 15;
    int g = (f == 0) ? 0 : ((f <= 11) ? 1 : 2);
    int bg = b*GG + g;
    int nz = g_znum[bg]; if (nz > ZCAP) nz = ZCAP;
    int t = threadIdx.x;             // 128 threads

    __shared__ float sXv[128];
    __shared__ float sXu[16][128];
    __shared__ float sAgg[128];
    __shared__ int   sUs[16];
    __shared__ int   sM;

    for (int i = slot; i < nz; i += 16){
        int vz = g_zlist[bg*ZCAP + i].y;
        bool dup = false;
        for (int jj = 0; jj < i; ++jj)
            if (g_zlist[bg*ZCAP + jj].y == vz){ dup = true; break; }
        if (dup) continue;

        if (t == 0){
            int m = 0;
            for (int jj = 0; jj < nz; ++jj){
                int2 e = g_zlist[bg*ZCAP + jj];
                if (e.y == vz && m < 16) sUs[m++] = e.x;
            }
            sM = m;
        }
        __syncthreads();
        int m = sM;

        sXv[t] = infos[(size_t)(b*2048 + t*16 + f)*512 + vz];
        for (int k = 0; k < m; ++k)
            sXu[k][t] = infos[(size_t)(b*2048 + t*16 + f)*512 + sUs[k]];
        __syncthreads();

        int c = t;
        float Dv = 0.0f;
        for (int e = 0; e < 128; ++e)
            Dv += sXv[e] * (Wd[c*384 + 128 + e] - Wd[c*384 + 256 + e]);
        float a1 = g_T1[bf*128 + c];
        float a2 = g_T2[bf*128 + c];
        for (int k = 0; k < m; ++k){
            float S = 0.0f;
            for (int e = 0; e < 128; ++e)
                S += sXu[k][e] * (Wd[c*384 + e] + Wd[c*384 + 256 + e]);
            a1 -= sXu[k][c] * S;
            a2 -= sXu[k][c];
        }
        int degi = 512 - g_zcnt[bg*NN + vz];
        float deg = (float)(degi > 1 ? degi : 1);
        sAgg[c] = (a1 + a2*(Dv + bd[c])) / deg;
        __syncthreads();

        float s = 0.0f;
        for (int cc = 0; cc < 128; ++cc) s += sAgg[cc] * Wn[t*128 + cc];
        s += bn[t];
        out[(size_t)(b*2048 + t*16 + f)*512 + vz] = fmaxf(s, 0.0f);
        __syncthreads();
    }
}

extern "C" void kernel_launch(void* const* d_in, const int* in_sizes, int n_in,
                              void* d_out, int out_size){
    const float* Y     = (const float*)d_in[0];
    const float* infos = (const float*)d_in[1];
    const float* Wd    = (const float*)d_in[2];
    const float* bd    = (const float*)d_in[3];
    const float* Wn    = (const float*)d_in[4];
    const float* bn    = (const float*)d_in[5];
    float* out = (float*)d_out;

    const int dynsm = 2 * 128 * ROWP * 4;   // 135168 bytes
    cudaFuncSetAttribute(k1_T,  cudaFuncAttributeMaxDynamicSharedMemorySize, dynsm);
    cudaFuncSetAttribute(k2_Q,  cudaFuncAttributeMaxDynamicSharedMemorySize, dynsm);
    cudaFuncSetAttribute(k3_out,cudaFuncAttributeMaxDynamicSharedMemorySize, dynsm);

    kinit<<<16, 256>>>();
    kscan<<<6144, 256>>>(Y);
    k1_T<<<128, 256, dynsm>>>(infos, Wd);
    k2_Q<<<128, 256, dynsm>>>(Wd, Wn, bd);
    k3_out<<<512, 256, dynsm>>>(infos, bn, out);
    k4_fix<<<dim3(16, 128), 128>>>(infos, Wd, bd, Wn, bn, out);
}

// round 5
// speedup vs baseline: 1.4975x; 1.4968x over previous
#include <cuda_runtime.h>
#include <cuda_bf16.h>
#include <cstdint>

typedef unsigned int u32;
typedef unsigned long long u64;
typedef unsigned short u16;

#define GG 3
#define ZCAP 4096
#define ST 136                 // bf16 elements per padded tile row (272 B)
#define TILEB (128*ST*2)       // 34816 bytes per 128x128 bf16 tile
#define DYNSM (4*TILEB)        // 139264

// ---------------- device scratch (allocation-free) ----------------
__device__ float g_T1[16384];
__device__ float g_T2[16384];
__device__ float g_k0[16384];
__device__ int   g_znum[24];
__device__ int   g_zcnt[24*512];
__device__ int2  g_zlist[24*ZCAP];
__device__ __align__(16) u32 g_Qh[128*8192];   // per-bf Q hi, bf16 [o][e] row-major (8192 u32/bf)
__device__ __align__(16) u32 g_Ql[128*8192];   // per-bf Q lo

// ---------------- helpers ----------------
static __device__ __forceinline__ u32 smem_u32(const void* p){
    u32 a;
    asm("{ .reg .u64 t; cvta.to.shared.u64 t, %1; cvt.u32.u64 %0, t; }" : "=r"(a) : "l"(p));
    return a;
}
#define LDSM_X4(r, a) \
    asm volatile("ldmatrix.sync.aligned.m8n8.x4.shared.b16 {%0,%1,%2,%3}, [%4];" \
        : "=r"((r)[0]),"=r"((r)[1]),"=r"((r)[2]),"=r"((r)[3]) : "r"(a))

static __device__ __forceinline__ void mma16816(float* c, const u32* a, const u32* b){
    asm volatile("mma.sync.aligned.m16n8k16.row.col.f32.bf16.bf16.f32 "
        "{%0,%1,%2,%3}, {%4,%5,%6,%7}, {%8,%9}, {%0,%1,%2,%3};"
        : "+f"(c[0]),"+f"(c[1]),"+f"(c[2]),"+f"(c[3])
        : "r"(a[0]),"r"(a[1]),"r"(a[2]),"r"(a[3]), "r"(b[0]),"r"(b[1]));
}
static __device__ __forceinline__ void bfsplit(float v, u16& h, u16& l){
    __nv_bfloat16 hb = __float2bfloat16(v);
    h = __bfloat16_as_ushort(hb);
    l = __bfloat16_as_ushort(__float2bfloat16(v - __bfloat162float(hb)));
}
static __device__ __forceinline__ void pack4(float4 x, u64& hv, u64& lv){
    u16 h0,l0,h1,l1,h2,l2,h3,l3;
    bfsplit(x.x,h0,l0); bfsplit(x.y,h1,l1); bfsplit(x.z,h2,l2); bfsplit(x.w,h3,l3);
    hv = (u64)h0 | ((u64)h1<<16) | ((u64)h2<<32) | ((u64)h3<<48);
    lv = (u64)l0 | ((u64)l1<<16) | ((u64)l2<<32) | ((u64)l3<<48);
}
static __device__ __forceinline__ float bf2f(u32 bits16){ return __uint_as_float(bits16 << 16); }

// 128x128x128 tile GEMM, 3 split products (hh, hl, lh), per-warp 32x64 output.
static __device__ __forceinline__ void gemm_tile(float acc[2][8][4], u32 aH, u32 aL, u32 bH, u32 bL){
    #pragma unroll
    for (int ks = 0; ks < 8; ++ks){
        u32 ah[2][4], al[2][4], bh[4][4], bl[4][4];
        #pragma unroll
        for (int mi = 0; mi < 2; ++mi){
            LDSM_X4(ah[mi], aH + mi*(16*ST*2) + ks*32);
            LDSM_X4(al[mi], aL + mi*(16*ST*2) + ks*32);
        }
        #pragma unroll
        for (int nj = 0; nj < 4; ++nj){
            LDSM_X4(bh[nj], bH + nj*(16*ST*2) + ks*32);
            LDSM_X4(bl[nj], bL + nj*(16*ST*2) + ks*32);
        }
        #pragma unroll
        for (int mi = 0; mi < 2; ++mi)
        #pragma unroll
        for (int nj = 0; nj < 4; ++nj){
            mma16816(acc[mi][nj*2],   ah[mi], &bh[nj][0]);
            mma16816(acc[mi][nj*2+1], ah[mi], &bh[nj][2]);
            mma16816(acc[mi][nj*2],   ah[mi], &bl[nj][0]);
            mma16816(acc[mi][nj*2+1], ah[mi], &bl[nj][2]);
            mma16816(acc[mi][nj*2],   al[mi], &bh[nj][0]);
            mma16816(acc[mi][nj*2+1], al[mi], &bh[nj][2]);
        }
    }
}

// -------- init: zero the zero-tracking state --------
__global__ void kinit(){
    int t = blockIdx.x*blockDim.x + threadIdx.x;
    if (t < 24) g_znum[t] = 0;
    for (int i = t; i < 24*512; i += 16*256) g_zcnt[i] = 0;
}

// -------- scan Y slices 0..2 for exact zeros --------
__global__ void kscan(const float* __restrict__ Y){
    int gtid = blockIdx.x*blockDim.x + threadIdx.x;
    int bg   = gtid >> 16;
    int off4 = gtid & 65535;
    int b = bg / GG, g = bg % GG;
    const float4 y4 = reinterpret_cast<const float4*>(Y)[(size_t)(b*16 + g)*65536 + off4];
    int l = off4 * 4;
    int u = l >> 9, v = l & 511;
    float vals[4] = {y4.x, y4.y, y4.z, y4.w};
    #pragma unroll
    for (int r = 0; r < 4; ++r){
        if (vals[r] == 0.0f){
            int pos = atomicAdd(&g_znum[bg], 1);
            if (pos < ZCAP) g_zlist[bg*ZCAP + pos] = make_int2(u, v + r);
            atomicAdd(&g_zcnt[bg*512 + v + r], 1);
        }
    }
}

// -------- K1: per (b,f): Gram MMA -> T1/T2, fused Q MMA -> Qhi/Qlo + k0 --------
__global__ void __launch_bounds__(256) k1_gram(const float* __restrict__ infos,
                                               const float* __restrict__ Wd,
                                               const float* __restrict__ bd,
                                               const float* __restrict__ Wn){
    extern __shared__ __align__(16) char smc[];
    __shared__ float sT1[128], sT2[128], sVec[128];

    int bf = blockIdx.x, b = bf >> 4, f = bf & 15;
    int t = threadIdx.x, wid = t >> 5, lane = t & 31;
    int wm = wid & 3, wn = wid >> 2;
    int m0 = wm*32, n0 = wn*64;
    int g = lane >> 2, t4 = lane & 3;

    u32 sb = smem_u32(smc);
    u32 aBase = sb + (u32)(((m0 + (lane & 15))*ST + (lane >> 4)*8) * 2);
    u32 bBase = sb + (u32)(((n0 + (lane & 7) + ((lane >> 4) & 1)*8)*ST + ((lane >> 3) & 1)*8) * 2);

    if (t < 128){ sT1[t] = 0.0f; sT2[t] = 0.0f; }

    // ---- Gram: G[c][c'] = sum_u X[u,c] X[u,c'], K=512 in 4 chunks ----
    int cr = t >> 1, uh = (t & 1)*64;
    const float* xrow = infos + (((size_t)b*128 + cr)*16 + f)*512;
    float t2acc = 0.0f;
    float acc[2][8][4] = {};

    for (int kk = 0; kk < 4; ++kk){
        __syncthreads();
        #pragma unroll
        for (int i = 0; i < 16; ++i){
            int ul = uh + i*4;
            float4 x = *reinterpret_cast<const float4*>(xrow + kk*128 + ul);
            t2acc += x.x + x.y + x.z + x.w;
            u64 hv, lv; pack4(x, hv, lv);
            *reinterpret_cast<u64*>(smc + (cr*ST + ul)*2)         = hv;
            *reinterpret_cast<u64*>(smc + TILEB + (cr*ST + ul)*2) = lv;
        }
        __syncthreads();
        gemm_tile(acc, aBase, aBase + TILEB, bBase, bBase + TILEB);
    }
    atomicAdd(&sT2[cr], t2acc);
    __syncthreads();

    // ---- WS = W1+W3 fp32 [128][129] at smem offset 0 (X tiles dead) ----
    {
        float* sWS = reinterpret_cast<float*>(smc);
        int d = t >> 1, ch = (t & 1)*64;
        #pragma unroll
        for (int i = 0; i < 16; ++i){
            int c0 = ch + i*4;
            float4 a  = *reinterpret_cast<const float4*>(Wd + d*384 + c0);
            float4 c3 = *reinterpret_cast<const float4*>(Wd + d*384 + 256 + c0);
            sWS[d*129 + c0 + 0] = a.x + c3.x;
            sWS[d*129 + c0 + 1] = a.y + c3.y;
            sWS[d*129 + c0 + 2] = a.z + c3.z;
            sWS[d*129 + c0 + 3] = a.w + c3.w;
        }
    }
    __syncthreads();

    // ---- T1 epilogue straight from Gram accumulators ----
    {
        const float* sWS = reinterpret_cast<const float*>(smc);
        #pragma unroll
        for (int mi = 0; mi < 2; ++mi){
            int r0 = m0 + mi*16 + g, r1 = r0 + 8;
            float s0 = 0.0f, s1 = 0.0f;
            #pragma unroll
            for (int ni = 0; ni < 8; ++ni){
                int col = n0 + ni*8 + 2*t4;
                s0 += acc[mi][ni][0]*sWS[r0*129 + col] + acc[mi][ni][1]*sWS[r0*129 + col + 1];
                s1 += acc[mi][ni][2]*sWS[r1*129 + col] + acc[mi][ni][3]*sWS[r1*129 + col + 1];
            }
            atomicAdd(&sT1[r0], s0);
            atomicAdd(&sT1[r1], s1);
        }
    }
    __syncthreads();
    if (t < 128){
        float t1v = sT1[t], t2v = sT2[t];
        g_T1[bf*128 + t] = t1v;
        g_T2[bf*128 + t] = t2v;
        sVec[t] = t1v + t2v * bd[t];
    }
    __syncthreads();

    // ---- build Wn tiles (hi@0, lo@TILEB) + BQ[e][c]=T2[c]*(W2-W3)[c,e] tiles ----
    {
        int o = t >> 1, ch = (t & 1)*64;
        #pragma unroll
        for (int i = 0; i < 16; ++i){
            int c0 = ch + i*4;
            float4 w = *reinterpret_cast<const float4*>(Wn + o*128 + c0);
            u64 hv, lv; pack4(w, hv, lv);
            *reinterpret_cast<u64*>(smc + (o*ST + c0)*2)         = hv;
            *reinterpret_cast<u64*>(smc + TILEB + (o*ST + c0)*2) = lv;
        }
    }
    {
        int c = t >> 1, eh = (t & 1)*64;
        float t2c = sT2[c];
        #pragma unroll
        for (int i = 0; i < 16; ++i){
            int e0 = eh + i*4;
            float4 a  = *reinterpret_cast<const float4*>(Wd + c*384 + 128 + e0);
            float4 c3 = *reinterpret_cast<const float4*>(Wd + c*384 + 256 + e0);
            float v[4] = {t2c*(a.x - c3.x), t2c*(a.y - c3.y), t2c*(a.z - c3.z), t2c*(a.w - c3.w)};
            #pragma unroll
            for (int j = 0; j < 4; ++j){
                u16 h, l; bfsplit(v[j], h, l);
                *reinterpret_cast<u16*>(smc + 2*TILEB + ((e0 + j)*ST + c)*2) = h;
                *reinterpret_cast<u16*>(smc + 3*TILEB + ((e0 + j)*ST + c)*2) = l;
            }
        }
    }
    __syncthreads();

    float qacc[2][8][4] = {};
    gemm_tile(qacc, aBase, aBase + TILEB, bBase + 2*TILEB, bBase + 3*TILEB);

    // ---- Q epilogue: split to bf16 hi/lo, plain [o][e] rows in gmem (8192 u32 per bf) ----
    #pragma unroll
    for (int mi = 0; mi < 2; ++mi){
        int r0 = m0 + mi*16 + g, r1 = r0 + 8;
        #pragma unroll
        for (int ni = 0; ni < 8; ++ni){
            int col = n0 + ni*8 + 2*t4;
            u16 h0,l0,h1,l1;
            bfsplit(qacc[mi][ni][0], h0, l0); bfsplit(qacc[mi][ni][1], h1, l1);
            g_Qh[bf*8192 + r0*64 + (col >> 1)] = (u32)h0 | ((u32)h1 << 16);
            g_Ql[bf*8192 + r0*64 + (col >> 1)] = (u32)l0 | ((u32)l1 << 16);
            bfsplit(qacc[mi][ni][2], h0, l0); bfsplit(qacc[mi][ni][3], h1, l1);
            g_Qh[bf*8192 + r1*64 + (col >> 1)] = (u32)h0 | ((u32)h1 << 16);
            g_Ql[bf*8192 + r1*64 + (col >> 1)] = (u32)l0 | ((u32)l1 << 16);
        }
    }

    // ---- k0[o] = sum_c Wn[o,c]*sVec[c] from smem Wn hi/lo tiles ----
    if (t < 128){
        float s = 0.0f;
        #pragma unroll 4
        for (int c2 = 0; c2 < 128; c2 += 2){
            u32 hw = *reinterpret_cast<const u32*>(smc + (t*ST + c2)*2);
            u32 lw = *reinterpret_cast<const u32*>(smc + TILEB + (t*ST + c2)*2);
            float w0 = bf2f(hw & 0xffff) + bf2f(lw & 0xffff);
            float w1 = bf2f(hw >> 16)    + bf2f(lw >> 16);
            s += w0*sVec[c2] + w1*sVec[c2 + 1];
        }
        g_k0[bf*128 + t] = s;
    }
}

// -------- K3: out[b,o,f,v] = relu(fma(X@Q^T, 1/512, k0/512 + bn)) --------
__global__ void __launch_bounds__(256) k3_out(const float* __restrict__ infos,
                                              const float* __restrict__ bn,
                                              float* __restrict__ out){
    extern __shared__ __align__(16) char smc[];
    __shared__ float sBase[128];

    int bid = blockIdx.x, bf = bid >> 2, vt = bid & 3, v0 = vt*128;
    int b = bf >> 4, f = bf & 15;
    int t = threadIdx.x, wid = t >> 5, lane = t & 31;
    int wm = wid & 3, wn = wid >> 2;
    int m0 = wm*32, n0 = wn*64;
    int g = lane >> 2, t4 = lane & 3;

    u32 sb = smem_u32(smc);
    u32 aBase = sb + (u32)(((m0 + (lane & 15))*ST + (lane >> 4)*8) * 2);
    u32 bBase = sb + 2*TILEB + (u32)(((n0 + (lane & 7) + ((lane >> 4) & 1)*8)*ST + ((lane >> 3) & 1)*8) * 2);

    if (t < 128) sBase[t] = g_k0[bf*128 + t]*(1.0f/512.0f) + bn[t];

    // A: X[v][e] tiles (transposed build from [e][v] gmem layout)
    {
        int e = t >> 1, vh = (t & 1)*64;
        const float* xr = infos + (((size_t)b*128 + e)*16 + f)*512 + v0;
        #pragma unroll
        for (int i = 0; i < 16; ++i){
            int r0 = vh + i*4;
            float4 x = *reinterpret_cast<const float4*>(xr + r0);
            float vv[4] = {x.x, x.y, x.z, x.w};
            #pragma unroll
            for (int j = 0; j < 4; ++j){
                u16 h, l; bfsplit(vv[j], h, l);
                *reinterpret_cast<u16*>(smc + ((r0 + j)*ST + e)*2)         = h;
                *reinterpret_cast<u16*>(smc + TILEB + ((r0 + j)*ST + e)*2) = l;
            }
        }
    }
    // B: Q hi/lo raw row copy into padded tiles
    {
        const u64* qh = reinterpret_cast<const u64*>(g_Qh + bf*8192);
        const u64* ql = reinterpret_cast<const u64*>(g_Ql + bf*8192);
        for (int i = t; i < 4096; i += 256){
            int row = i >> 5, c8 = i & 31;
            *reinterpret_cast<u64*>(smc + 2*TILEB + row*ST*2 + c8*8) = qh[i];
            *reinterpret_cast<u64*>(smc + 3*TILEB + row*ST*2 + c8*8) = ql[i];
        }
    }
    __syncthreads();

    float acc[2][8][4] = {};
    gemm_tile(acc, aBase, aBase + TILEB, bBase, bBase + TILEB);

    const float inv = 1.0f/512.0f;
    #pragma unroll
    for (int mi = 0; mi < 2; ++mi){
        int r0 = m0 + mi*16 + g, r1 = r0 + 8;
        #pragma unroll
        for (int ni = 0; ni < 8; ++ni){
            int col = n0 + ni*8 + 2*t4;
            size_t o0 = ((size_t)(b*128 + col)*16 + f)*512 + v0;
            size_t o1 = o0 + (size_t)16*512;
            out[o0 + r0] = fmaxf(fmaf(acc[mi][ni][0], inv, sBase[col]),     0.0f);
            out[o1 + r0] = fmaxf(fmaf(acc[mi][ni][1], inv, sBase[col + 1]), 0.0f);
            out[o0 + r1] = fmaxf(fmaf(acc[mi][ni][2], inv, sBase[col]),     0.0f);
            out[o1 + r1] = fmaxf(fmaf(acc[mi][ni][3], inv, sBase[col + 1]), 0.0f);
        }
    }
}

// -------- K4: exact recompute of the rare zero-affected output columns --------
__global__ void k4_fix(const float* __restrict__ infos, const float* __restrict__ Wd,
                       const float* __restrict__ bd, const float* __restrict__ Wn,
                       const float* __restrict__ bn, float* __restrict__ out){
    int slot = blockIdx.x;
    int bf   = blockIdx.y;
    int b = bf >> 4, f = bf & 15;
    int g = (f == 0) ? 0 : ((f <= 11) ? 1 : 2);
    int bg = b*GG + g;
    int nz = g_znum[bg]; if (nz > ZCAP) nz = ZCAP;
    int t = threadIdx.x;

    __shared__ float sXv[128];
    __shared__ float sXu[16][128];
    __shared__ float sAgg[128];
    __shared__ int   sUs[16];
    __shared__ int   sM;

    for (int i = slot; i < nz; i += 16){
        int vz = g_zlist[bg*ZCAP + i].y;
        bool dup = false;
        for (int jj = 0; jj < i; ++jj)
            if (g_zlist[bg*ZCAP + jj].y == vz){ dup = true; break; }
        if (dup) continue;

        if (t == 0){
            int m = 0;
            for (int jj = 0; jj < nz; ++jj){
                int2 e = g_zlist[bg*ZCAP + jj];
                if (e.y == vz && m < 16) sUs[m++] = e.x;
            }
            sM = m;
        }
        __syncthreads();
        int m = sM;

        sXv[t] = infos[(size_t)(b*2048 + t*16 + f)*512 + vz];
        for (int k = 0; k < m; ++k)
            sXu[k][t] = infos[(size_t)(b*2048 + t*16 + f)*512 + sUs[k]];
        __syncthreads();

        int c = t;
        float Dv = 0.0f;
        for (int e = 0; e < 128; ++e)
            Dv += sXv[e] * (Wd[c*384 + 128 + e] - Wd[c*384 + 256 + e]);
        float a1 = g_T1[bf*128 + c];
        float a2 = g_T2[bf*128 + c];
        for (int k = 0; k < m; ++k){
            float S = 0.0f;
            for (int e = 0; e < 128; ++e)
                S += sXu[k][e] * (Wd[c*384 + e] + Wd[c*384 + 256 + e]);
            a1 -= sXu[k][c] * S;
            a2 -= sXu[k][c];
        }
        int degi = 512 - g_zcnt[bg*512 + vz];
        float deg = (float)(degi > 1 ? degi : 1);
        sAgg[c] = (a1 + a2*(Dv + bd[c])) / deg;
        __syncthreads();

        float s = 0.0f;
        for (int cc = 0; cc < 128; ++cc) s += sAgg[cc] * Wn[t*128 + cc];
        s += bn[t];
        out[(size_t)(b*2048 + t*16 + f)*512 + vz] = fmaxf(s, 0.0f);
        __syncthreads();
    }
}

extern "C" void kernel_launch(void* const* d_in, const int* in_sizes, int n_in,
                              void* d_out, int out_size){
    const float* Y     = (const float*)d_in[0];
    const float* infos = (const float*)d_in[1];
    const float* Wd    = (const float*)d_in[2];
    const float* bd    = (const float*)d_in[3];
    const float* Wn    = (const float*)d_in[4];
    const float* bn    = (const float*)d_in[5];
    float* out = (float*)d_out;

    cudaFuncSetAttribute(k1_gram, cudaFuncAttributeMaxDynamicSharedMemorySize, DYNSM);
    cudaFuncSetAttribute(k3_out,  cudaFuncAttributeMaxDynamicSharedMemorySize, DYNSM);

    kinit<<<16, 256>>>();
    kscan<<<6144, 256>>>(Y);
    k1_gram<<<128, 256, DYNSM>>>(infos, Wd, bd, Wn);
    k3_out<<<512, 256, DYNSM>>>(infos, bn, out);
    k4_fix<<<dim3(16, 128), 128>>>(infos, Wd, bd, Wn, bn, out);
}

// round 6
// speedup vs baseline: 1.5224x; 1.0166x over previous
#include <cuda_runtime.h>
#include <cuda_bf16.h>
#include <cstdint>

typedef unsigned int u32;
typedef unsigned long long u64;
typedef unsigned short u16;

#define GG 3
#define ZCAP 4096
#define ST 136                 // bf16 elements per padded tile row (272 B)
#define TILEB (128*ST*2)       // 34816 bytes per 128x128 bf16 tile
#define DYNSM (4*TILEB)        // 139264

// ---------------- device scratch (allocation-free) ----------------
__device__ float g_T1[16384];
__device__ float g_T2[16384];
__device__ float g_k0[16384];
__device__ int   g_znum[24];
__device__ int   g_zcnt[24*512];
__device__ int2  g_zlist[24*ZCAP];
__device__ __align__(16) u32 g_Qh[128*8192];   // per-bf Q hi, bf16 [o][e] row-major
__device__ __align__(16) u32 g_Ql[128*8192];   // per-bf Q lo

// ---------------- helpers ----------------
static __device__ __forceinline__ u32 smem_u32(const void* p){
    u32 a;
    asm("{ .reg .u64 t; cvta.to.shared.u64 t, %1; cvt.u32.u64 %0, t; }" : "=r"(a) : "l"(p));
    return a;
}
#define LDSM_X4(r, a) \
    asm volatile("ldmatrix.sync.aligned.m8n8.x4.shared.b16 {%0,%1,%2,%3}, [%4];" \
        : "=r"((r)[0]),"=r"((r)[1]),"=r"((r)[2]),"=r"((r)[3]) : "r"(a))

static __device__ __forceinline__ void mma16816(float* c, const u32* a, const u32* b){
    asm volatile("mma.sync.aligned.m16n8k16.row.col.f32.bf16.bf16.f32 "
        "{%0,%1,%2,%3}, {%4,%5,%6,%7}, {%8,%9}, {%0,%1,%2,%3};"
        : "+f"(c[0]),"+f"(c[1]),"+f"(c[2]),"+f"(c[3])
        : "r"(a[0]),"r"(a[1]),"r"(a[2]),"r"(a[3]), "r"(b[0]),"r"(b[1]));
}
static __device__ __forceinline__ void bfsplit(float v, u16& h, u16& l){
    __nv_bfloat16 hb = __float2bfloat16(v);
    h = __bfloat16_as_ushort(hb);
    l = __bfloat16_as_ushort(__float2bfloat16(v - __bfloat162float(hb)));
}
static __device__ __forceinline__ void pack4(float4 x, u64& hv, u64& lv){
    u16 h0,l0,h1,l1,h2,l2,h3,l3;
    bfsplit(x.x,h0,l0); bfsplit(x.y,h1,l1); bfsplit(x.z,h2,l2); bfsplit(x.w,h3,l3);
    hv = (u64)h0 | ((u64)h1<<16) | ((u64)h2<<32) | ((u64)h3<<48);
    lv = (u64)l0 | ((u64)l1<<16) | ((u64)l2<<32) | ((u64)l3<<48);
}
static __device__ __forceinline__ float bf2f(u32 bits16){ return __uint_as_float(bits16 << 16); }

// 128x128x128 tile GEMM, 3 split products (hh, hl, lh).
// 16 warps, each computes a 32x32 output tile. acc[2][4][4]: mi (16 rows), ns (8 cols).
static __device__ __forceinline__ void gemm_tile(float acc[2][4][4], u32 aH, u32 aL, u32 bH, u32 bL){
    #pragma unroll
    for (int ks = 0; ks < 8; ++ks){
        u32 ah[2][4], al[2][4], bh[2][4], bl[2][4];
        #pragma unroll
        for (int mi = 0; mi < 2; ++mi){
            LDSM_X4(ah[mi], aH + mi*(16*ST*2) + ks*32);
            LDSM_X4(al[mi], aL + mi*(16*ST*2) + ks*32);
        }
        #pragma unroll
        for (int nj = 0; nj < 2; ++nj){
            LDSM_X4(bh[nj], bH + nj*(16*ST*2) + ks*32);
            LDSM_X4(bl[nj], bL + nj*(16*ST*2) + ks*32);
        }
        // pass 1: hh (8 independent chains)
        #pragma unroll
        for (int mi = 0; mi < 2; ++mi)
        #pragma unroll
        for (int nj = 0; nj < 2; ++nj){
            mma16816(acc[mi][nj*2],   ah[mi], &bh[nj][0]);
            mma16816(acc[mi][nj*2+1], ah[mi], &bh[nj][2]);
        }
        // pass 2: hl
        #pragma unroll
        for (int mi = 0; mi < 2; ++mi)
        #pragma unroll
        for (int nj = 0; nj < 2; ++nj){
            mma16816(acc[mi][nj*2],   ah[mi], &bl[nj][0]);
            mma16816(acc[mi][nj*2+1], ah[mi], &bl[nj][2]);
        }
        // pass 3: lh
        #pragma unroll
        for (int mi = 0; mi < 2; ++mi)
        #pragma unroll
        for (int nj = 0; nj < 2; ++nj){
            mma16816(acc[mi][nj*2],   al[mi], &bh[nj][0]);
            mma16816(acc[mi][nj*2+1], al[mi], &bh[nj][2]);
        }
    }
}

// -------- init: zero the zero-tracking state --------
__global__ void kinit(){
    int t = blockIdx.x*blockDim.x + threadIdx.x;
    if (t < 24) g_znum[t] = 0;
    for (int i = t; i < 24*512; i += 16*256) g_zcnt[i] = 0;
}

// -------- scan Y slices 0..2 for exact zeros --------
__global__ void kscan(const float* __restrict__ Y){
    int gtid = blockIdx.x*blockDim.x + threadIdx.x;
    int bg   = gtid >> 16;
    int off4 = gtid & 65535;
    int b = bg / GG, g = bg % GG;
    const float4 y4 = reinterpret_cast<const float4*>(Y)[(size_t)(b*16 + g)*65536 + off4];
    int l = off4 * 4;
    int u = l >> 9, v = l & 511;
    float vals[4] = {y4.x, y4.y, y4.z, y4.w};
    #pragma unroll
    for (int r = 0; r < 4; ++r){
        if (vals[r] == 0.0f){
            int pos = atomicAdd(&g_znum[bg], 1);
            if (pos < ZCAP) g_zlist[bg*ZCAP + pos] = make_int2(u, v + r);
            atomicAdd(&g_zcnt[bg*512 + v + r], 1);
        }
    }
}

// -------- K1: per (b,f): Gram MMA -> T1/T2, fused Q MMA -> Qhi/Qlo + k0 --------
__global__ void __launch_bounds__(512, 1) k1_gram(const float* __restrict__ infos,
                                                  const float* __restrict__ Wd,
                                                  const float* __restrict__ bd,
                                                  const float* __restrict__ Wn){
    extern __shared__ __align__(16) char smc[];
    __shared__ float sT1[128], sT2[128], sVec[128];

    int bf = blockIdx.x, b = bf >> 4, f = bf & 15;
    int t = threadIdx.x, wid = t >> 5, lane = t & 31;
    int wm = wid & 3, wn = wid >> 2;          // wn: 0..3
    int m0 = wm*32, n0 = wn*32;
    int g = lane >> 2, t4 = lane & 3;

    u32 sb = smem_u32(smc);
    u32 aBase = sb + (u32)(((m0 + (lane & 15))*ST + (lane >> 4)*8) * 2);
    u32 bBase = sb + (u32)(((n0 + (lane & 7) + ((lane >> 4) & 1)*8)*ST + ((lane >> 3) & 1)*8) * 2);

    if (t < 128){ sT1[t] = 0.0f; sT2[t] = 0.0f; }

    // ---- Gram: G[c][c'] = sum_u X[u,c] X[u,c'], K=512 in 4 chunks ----
    int cr = t >> 2, uh = (t & 3)*32;
    const float* xrow = infos + (((size_t)b*128 + cr)*16 + f)*512;
    float t2acc = 0.0f;
    float acc[2][4][4] = {};

    for (int kk = 0; kk < 4; ++kk){
        __syncthreads();
        #pragma unroll
        for (int i = 0; i < 8; ++i){
            int ul = uh + i*4;
            float4 x = *reinterpret_cast<const float4*>(xrow + kk*128 + ul);
            t2acc += x.x + x.y + x.z + x.w;
            u64 hv, lv; pack4(x, hv, lv);
            *reinterpret_cast<u64*>(smc + (cr*ST + ul)*2)         = hv;
            *reinterpret_cast<u64*>(smc + TILEB + (cr*ST + ul)*2) = lv;
        }
        __syncthreads();
        gemm_tile(acc, aBase, aBase + TILEB, bBase, bBase + TILEB);
    }
    atomicAdd(&sT2[cr], t2acc);
    __syncthreads();

    // ---- WS = W1+W3 fp32 [128][129] at smem offset 0 (X tiles dead) ----
    {
        float* sWS = reinterpret_cast<float*>(smc);
        int d = t >> 2, ch = (t & 3)*32;
        #pragma unroll
        for (int i = 0; i < 8; ++i){
            int c0 = ch + i*4;
            float4 a  = *reinterpret_cast<const float4*>(Wd + d*384 + c0);
            float4 c3 = *reinterpret_cast<const float4*>(Wd + d*384 + 256 + c0);
            sWS[d*129 + c0 + 0] = a.x + c3.x;
            sWS[d*129 + c0 + 1] = a.y + c3.y;
            sWS[d*129 + c0 + 2] = a.z + c3.z;
            sWS[d*129 + c0 + 3] = a.w + c3.w;
        }
    }
    __syncthreads();

    // ---- T1 epilogue straight from Gram accumulators ----
    {
        const float* sWS = reinterpret_cast<const float*>(smc);
        #pragma unroll
        for (int mi = 0; mi < 2; ++mi){
            int r0 = m0 + mi*16 + g, r1 = r0 + 8;
            float s0 = 0.0f, s1 = 0.0f;
            #pragma unroll
            for (int ni = 0; ni < 4; ++ni){
                int col = n0 + ni*8 + 2*t4;
                s0 += acc[mi][ni][0]*sWS[r0*129 + col] + acc[mi][ni][1]*sWS[r0*129 + col + 1];
                s1 += acc[mi][ni][2]*sWS[r1*129 + col] + acc[mi][ni][3]*sWS[r1*129 + col + 1];
            }
            atomicAdd(&sT1[r0], s0);
            atomicAdd(&sT1[r1], s1);
        }
    }
    __syncthreads();
    if (t < 128){
        float t1v = sT1[t], t2v = sT2[t];
        g_T1[bf*128 + t] = t1v;
        g_T2[bf*128 + t] = t2v;
        sVec[t] = t1v + t2v * bd[t];
    }
    __syncthreads();

    // ---- build Wn tiles (hi@0, lo@TILEB) + BQ[e][c]=T2[c]*(W2-W3)[c,e] tiles ----
    {
        int o = t >> 2, ch = (t & 3)*32;
        #pragma unroll
        for (int i = 0; i < 8; ++i){
            int c0 = ch + i*4;
            float4 w = *reinterpret_cast<const float4*>(Wn + o*128 + c0);
            u64 hv, lv; pack4(w, hv, lv);
            *reinterpret_cast<u64*>(smc + (o*ST + c0)*2)         = hv;
            *reinterpret_cast<u64*>(smc + TILEB + (o*ST + c0)*2) = lv;
        }
    }
    {
        int c = t >> 2, eh = (t & 3)*32;
        float t2c = sT2[c];
        #pragma unroll
        for (int i = 0; i < 8; ++i){
            int e0 = eh + i*4;
            float4 a  = *reinterpret_cast<const float4*>(Wd + c*384 + 128 + e0);
            float4 c3 = *reinterpret_cast<const float4*>(Wd + c*384 + 256 + e0);
            float v[4] = {t2c*(a.x - c3.x), t2c*(a.y - c3.y), t2c*(a.z - c3.z), t2c*(a.w - c3.w)};
            #pragma unroll
            for (int j = 0; j < 4; ++j){
                u16 h, l; bfsplit(v[j], h, l);
                *reinterpret_cast<u16*>(smc + 2*TILEB + ((e0 + j)*ST + c)*2) = h;
                *reinterpret_cast<u16*>(smc + 3*TILEB + ((e0 + j)*ST + c)*2) = l;
            }
        }
    }
    __syncthreads();

    float qacc[2][4][4] = {};
    gemm_tile(qacc, aBase, aBase + TILEB, bBase + 2*TILEB, bBase + 3*TILEB);

    // ---- Q epilogue: split to bf16 hi/lo, plain [o][e] rows in gmem ----
    #pragma unroll
    for (int mi = 0; mi < 2; ++mi){
        int r0 = m0 + mi*16 + g, r1 = r0 + 8;
        #pragma unroll
        for (int ni = 0; ni < 4; ++ni){
            int col = n0 + ni*8 + 2*t4;
            u16 h0,l0,h1,l1;
            bfsplit(qacc[mi][ni][0], h0, l0); bfsplit(qacc[mi][ni][1], h1, l1);
            g_Qh[bf*8192 + r0*64 + (col >> 1)] = (u32)h0 | ((u32)h1 << 16);
            g_Ql[bf*8192 + r0*64 + (col >> 1)] = (u32)l0 | ((u32)l1 << 16);
            bfsplit(qacc[mi][ni][2], h0, l0); bfsplit(qacc[mi][ni][3], h1, l1);
            g_Qh[bf*8192 + r1*64 + (col >> 1)] = (u32)h0 | ((u32)h1 << 16);
            g_Ql[bf*8192 + r1*64 + (col >> 1)] = (u32)l0 | ((u32)l1 << 16);
        }
    }

    // ---- k0[o] = sum_c Wn[o,c]*sVec[c] from smem Wn hi/lo tiles ----
    if (t < 128){
        float s = 0.0f;
        #pragma unroll 4
        for (int c2 = 0; c2 < 128; c2 += 2){
            u32 hw = *reinterpret_cast<const u32*>(smc + (t*ST + c2)*2);
            u32 lw = *reinterpret_cast<const u32*>(smc + TILEB + (t*ST + c2)*2);
            float w0 = bf2f(hw & 0xffff) + bf2f(lw & 0xffff);
            float w1 = bf2f(hw >> 16)    + bf2f(lw >> 16);
            s += w0*sVec[c2] + w1*sVec[c2 + 1];
        }
        g_k0[bf*128 + t] = s;
    }
}

// -------- K3: out[b,o,f,v] = relu(fma(X@Q^T, 1/512, k0/512 + bn)) --------
__global__ void __launch_bounds__(512, 1) k3_out(const float* __restrict__ infos,
                                                 const float* __restrict__ bn,
                                                 float* __restrict__ out){
    extern __shared__ __align__(16) char smc[];
    __shared__ float sBase[128];

    int bid = blockIdx.x, bf = bid >> 2, vt = bid & 3, v0 = vt*128;
    int b = bf >> 4, f = bf & 15;
    int t = threadIdx.x, wid = t >> 5, lane = t & 31;
    int wm = wid & 3, wn = wid >> 2;
    int m0 = wm*32, n0 = wn*32;
    int g = lane >> 2, t4 = lane & 3;

    u32 sb = smem_u32(smc);
    u32 aBase = sb + (u32)(((m0 + (lane & 15))*ST + (lane >> 4)*8) * 2);
    u32 bBase = sb + 2*TILEB + (u32)(((n0 + (lane & 7) + ((lane >> 4) & 1)*8)*ST + ((lane >> 3) & 1)*8) * 2);

    if (t < 128) sBase[t] = g_k0[bf*128 + t]*(1.0f/512.0f) + bn[t];

    // A: X[v][e] tiles (transposed build from [e][v] gmem layout)
    {
        int e = t >> 2, vh = (t & 3)*32;
        const float* xr = infos + (((size_t)b*128 + e)*16 + f)*512 + v0;
        #pragma unroll
        for (int i = 0; i < 8; ++i){
            int r0 = vh + i*4;
            float4 x = *reinterpret_cast<const float4*>(xr + r0);
            float vv[4] = {x.x, x.y, x.z, x.w};
            #pragma unroll
            for (int j = 0; j < 4; ++j){
                u16 h, l; bfsplit(vv[j], h, l);
                *reinterpret_cast<u16*>(smc + ((r0 + j)*ST + e)*2)         = h;
                *reinterpret_cast<u16*>(smc + TILEB + ((r0 + j)*ST + e)*2) = l;
            }
        }
    }
    // B: Q hi/lo raw row copy into padded tiles
    {
        const u64* qh = reinterpret_cast<const u64*>(g_Qh + bf*8192);
        const u64* ql = reinterpret_cast<const u64*>(g_Ql + bf*8192);
        for (int i = t; i < 4096; i += 512){
            int row = i >> 5, c8 = i & 31;
            *reinterpret_cast<u64*>(smc + 2*TILEB + row*ST*2 + c8*8) = qh[i];
            *reinterpret_cast<u64*>(smc + 3*TILEB + row*ST*2 + c8*8) = ql[i];
        }
    }
    __syncthreads();

    float acc[2][4][4] = {};
    gemm_tile(acc, aBase, aBase + TILEB, bBase, bBase + TILEB);

    const float inv = 1.0f/512.0f;
    #pragma unroll
    for (int mi = 0; mi < 2; ++mi){
        int r0 = m0 + mi*16 + g, r1 = r0 + 8;
        #pragma unroll
        for (int ni = 0; ni < 4; ++ni){
            int col = n0 + ni*8 + 2*t4;
            size_t o0 = ((size_t)(b*128 + col)*16 + f)*512 + v0;
            size_t o1 = o0 + (size_t)16*512;
            out[o0 + r0] = fmaxf(fmaf(acc[mi][ni][0], inv, sBase[col]),     0.0f);
            out[o1 + r0] = fmaxf(fmaf(acc[mi][ni][1], inv, sBase[col + 1]), 0.0f);
            out[o0 + r1] = fmaxf(fmaf(acc[mi][ni][2], inv, sBase[col]),     0.0f);
            out[o1 + r1] = fmaxf(fmaf(acc[mi][ni][3], inv, sBase[col + 1]), 0.0f);
        }
    }
}

// -------- K4: exact recompute of the rare zero-affected output columns --------
__global__ void k4_fix(const float* __restrict__ infos, const float* __restrict__ Wd,
                       const float* __restrict__ bd, const float* __restrict__ Wn,
                       const float* __restrict__ bn, float* __restrict__ out){
    int slot = blockIdx.x;
    int bf   = blockIdx.y;
    int b = bf >> 4, f = bf & 15;
    int g = (f == 0) ? 0 : ((f <= 11) ? 1 : 2);
    int bg = b*GG + g;
    int nz = g_znum[bg]; if (nz > ZCAP) nz = ZCAP;
    int t = threadIdx.x;

    __shared__ float sXv[128];
    __shared__ float sXu[16][128];
    __shared__ float sAgg[128];
    __shared__ int   sUs[16];
    __shared__ int   sM;

    for (int i = slot; i < nz; i += 16){
        int vz = g_zlist[bg*ZCAP + i].y;
        bool dup = false;
        for (int jj = 0; jj < i; ++jj)
            if (g_zlist[bg*ZCAP + jj].y == vz){ dup = true; break; }
        if (dup) continue;

        if (t == 0){
            int m = 0;
            for (int jj = 0; jj < nz; ++jj){
                int2 e = g_zlist[bg*ZCAP + jj];
                if (e.y == vz && m < 16) sUs[m++] = e.x;
            }
            sM = m;
        }
        __syncthreads();
        int m = sM;

        sXv[t] = infos[(size_t)(b*2048 + t*16 + f)*512 + vz];
        for (int k = 0; k < m; ++k)
            sXu[k][t] = infos[(size_t)(b*2048 + t*16 + f)*512 + sUs[k]];
        __syncthreads();

        int c = t;
        float Dv = 0.0f;
        for (int e = 0; e < 128; ++e)
            Dv += sXv[e] * (Wd[c*384 + 128 + e] - Wd[c*384 + 256 + e]);
        float a1 = g_T1[bf*128 + c];
        float a2 = g_T2[bf*128 + c];
        for (int k = 0; k < m; ++k){
            float S = 0.0f;
            for (int e = 0; e < 128; ++e)
                S += sXu[k][e] * (Wd[c*384 + e] + Wd[c*384 + 256 + e]);
            a1 -= sXu[k][c] * S;
            a2 -= sXu[k][c];
        }
        int degi = 512 - g_zcnt[bg*512 + vz];
        float deg = (float)(degi > 1 ? degi : 1);
        sAgg[c] = (a1 + a2*(Dv + bd[c])) / deg;
        __syncthreads();

        float s = 0.0f;
        for (int cc = 0; cc < 128; ++cc) s += sAgg[cc] * Wn[t*128 + cc];
        s += bn[t];
        out[(size_t)(b*2048 + t*16 + f)*512 + vz] = fmaxf(s, 0.0f);
        __syncthreads();
    }
}

extern "C" void kernel_launch(void* const* d_in, const int* in_sizes, int n_in,
                              void* d_out, int out_size){
    const float* Y     = (const float*)d_in[0];
    const float* infos = (const float*)d_in[1];
    const float* Wd    = (const float*)d_in[2];
    const float* bd    = (const float*)d_in[3];
    const float* Wn    = (const float*)d_in[4];
    const float* bn    = (const float*)d_in[5];
    float* out = (float*)d_out;

    cudaFuncSetAttribute(k1_gram, cudaFuncAttributeMaxDynamicSharedMemorySize, DYNSM);
    cudaFuncSetAttribute(k3_out,  cudaFuncAttributeMaxDynamicSharedMemorySize, DYNSM);

    kinit<<<16, 256>>>();
    kscan<<<6144, 256>>>(Y);
    k1_gram<<<128, 512, DYNSM>>>(infos, Wd, bd, Wn);
    k3_out<<<512, 512, DYNSM>>>(infos, bn, out);
    k4_fix<<<dim3(16, 128), 128>>>(infos, Wd, bd, Wn, bn, out);
}

// round 8
// speedup vs baseline: 1.7171x; 1.1279x over previous
#include <cuda_runtime.h>
#include <cuda_bf16.h>
#include <cstdint>

typedef unsigned int u32;
typedef unsigned long long u64;
typedef unsigned short u16;

#define GG 3
#define ZCAP 4096
#define ST 136                 // bf16 elements per padded tile row (272 B)
#define TILEB (128*ST*2)       // 34816 bytes per 128x128 bf16 tile
#define DYNSM (4*TILEB)        // 139264

// ---------------- device scratch (allocation-free) ----------------
__device__ float g_T1[16384];
__device__ float g_T2[16384];
__device__ float g_k0[16384];
__device__ int   g_znum[24];
__device__ int   g_zcnt[24*512];
__device__ int2  g_zlist[24*ZCAP];
__device__ __align__(16) u32 g_Qh[128*8192];   // per-bf Q hi, bf16 [o][e] row-major
__device__ __align__(16) u32 g_Ql[128*8192];   // per-bf Q lo

// ---------------- helpers ----------------
static __device__ __forceinline__ u32 smem_u32(const void* p){
    u32 a;
    asm("{ .reg .u64 t; cvta.to.shared.u64 t, %1; cvt.u32.u64 %0, t; }" : "=r"(a) : "l"(p));
    return a;
}
#define LDSM_X4(r, a) \
    asm volatile("ldmatrix.sync.aligned.m8n8.x4.shared.b16 {%0,%1,%2,%3}, [%4];" \
        : "=r"((r)[0]),"=r"((r)[1]),"=r"((r)[2]),"=r"((r)[3]) : "r"(a))
#define LDSM_X4_T(r, a) \
    asm volatile("ldmatrix.sync.aligned.m8n8.x4.trans.shared.b16 {%0,%1,%2,%3}, [%4];" \
        : "=r"((r)[0]),"=r"((r)[1]),"=r"((r)[2]),"=r"((r)[3]) : "r"(a))

static __device__ __forceinline__ void mma16816(float* c, const u32* a, const u32* b){
    asm volatile("mma.sync.aligned.m16n8k16.row.col.f32.bf16.bf16.f32 "
        "{%0,%1,%2,%3}, {%4,%5,%6,%7}, {%8,%9}, {%0,%1,%2,%3};"
        : "+f"(c[0]),"+f"(c[1]),"+f"(c[2]),"+f"(c[3])
        : "r"(a[0]),"r"(a[1]),"r"(a[2]),"r"(a[3]), "r"(b[0]),"r"(b[1]));
}
static __device__ __forceinline__ void bfsplit(float v, u16& h, u16& l){
    __nv_bfloat16 hb = __float2bfloat16(v);
    h = __bfloat16_as_ushort(hb);
    l = __bfloat16_as_ushort(__float2bfloat16(v - __bfloat162float(hb)));
}
static __device__ __forceinline__ void pack4(float4 x, u64& hv, u64& lv){
    u16 h0,l0,h1,l1,h2,l2,h3,l3;
    bfsplit(x.x,h0,l0); bfsplit(x.y,h1,l1); bfsplit(x.z,h2,l2); bfsplit(x.w,h3,l3);
    hv = (u64)h0 | ((u64)h1<<16) | ((u64)h2<<32) | ((u64)h3<<48);
    lv = (u64)l0 | ((u64)l1<<16) | ((u64)l2<<32) | ((u64)l3<<48);
}
static __device__ __forceinline__ float bf2f(u32 bits16){ return __uint_as_float(bits16 << 16); }

// non-trans gemm (A [m][k] rows, B [n][k] rows), 3 split products, warp 32x32 tile
static __device__ __forceinline__ void gemm_tile(float acc[2][4][4], u32 aH, u32 aL, u32 bH, u32 bL){
    #pragma unroll
    for (int ks = 0; ks < 8; ++ks){
        u32 ah[2][4], al[2][4], bh[2][4], bl[2][4];
        #pragma unroll
        for (int mi = 0; mi < 2; ++mi){
            LDSM_X4(ah[mi], aH + mi*(16*ST*2) + ks*32);
            LDSM_X4(al[mi], aL + mi*(16*ST*2) + ks*32);
        }
        #pragma unroll
        for (int nj = 0; nj < 2; ++nj){
            LDSM_X4(bh[nj], bH + nj*(16*ST*2) + ks*32);
            LDSM_X4(bl[nj], bL + nj*(16*ST*2) + ks*32);
        }
        #pragma unroll
        for (int mi = 0; mi < 2; ++mi)
        #pragma unroll
        for (int nj = 0; nj < 2; ++nj){
            mma16816(acc[mi][nj*2],   ah[mi], &bh[nj][0]);
            mma16816(acc[mi][nj*2+1], ah[mi], &bh[nj][2]);
        }
        #pragma unroll
        for (int mi = 0; mi < 2; ++mi)
        #pragma unroll
        for (int nj = 0; nj < 2; ++nj){
            mma16816(acc[mi][nj*2],   ah[mi], &bl[nj][0]);
            mma16816(acc[mi][nj*2+1], ah[mi], &bl[nj][2]);
        }
        #pragma unroll
        for (int mi = 0; mi < 2; ++mi)
        #pragma unroll
        for (int nj = 0; nj < 2; ++nj){
            mma16816(acc[mi][nj*2],   al[mi], &bh[nj][0]);
            mma16816(acc[mi][nj*2+1], al[mi], &bh[nj][2]);
        }
    }
}

// trans-B gemm (A [m][k] rows, B [k][n] rows via ldmatrix.trans)
static __device__ __forceinline__ void gemm_tile_tb(float acc[2][4][4], u32 aH, u32 aL, u32 bH, u32 bL){
    #pragma unroll
    for (int ks = 0; ks < 8; ++ks){
        u32 ah[2][4], al[2][4], bh[2][4], bl[2][4];
        #pragma unroll
        for (int mi = 0; mi < 2; ++mi){
            LDSM_X4(ah[mi], aH + mi*(16*ST*2) + ks*32);
            LDSM_X4(al[mi], aL + mi*(16*ST*2) + ks*32);
        }
        #pragma unroll
        for (int nj = 0; nj < 2; ++nj){
            LDSM_X4_T(bh[nj], bH + nj*32 + ks*(16*ST*2));
            LDSM_X4_T(bl[nj], bL + nj*32 + ks*(16*ST*2));
        }
        #pragma unroll
        for (int mi = 0; mi < 2; ++mi)
        #pragma unroll
        for (int nj = 0; nj < 2; ++nj){
            mma16816(acc[mi][nj*2],   ah[mi], &bh[nj][0]);
            mma16816(acc[mi][nj*2+1], ah[mi], &bh[nj][2]);
        }
        #pragma unroll
        for (int mi = 0; mi < 2; ++mi)
        #pragma unroll
        for (int nj = 0; nj < 2; ++nj){
            mma16816(acc[mi][nj*2],   ah[mi], &bl[nj][0]);
            mma16816(acc[mi][nj*2+1], ah[mi], &bl[nj][2]);
        }
        #pragma unroll
        for (int mi = 0; mi < 2; ++mi)
        #pragma unroll
        for (int nj = 0; nj < 2; ++nj){
            mma16816(acc[mi][nj*2],   al[mi], &bh[nj][0]);
            mma16816(acc[mi][nj*2+1], al[mi], &bh[nj][2]);
        }
    }
}

// -------- init --------
__global__ void kinit(){
    int t = blockIdx.x*blockDim.x + threadIdx.x;
    if (t < 24) g_znum[t] = 0;
    for (int i = t; i < 24*512; i += 16*256) g_zcnt[i] = 0;
}

// -------- scan Y slices 0..2 for exact zeros --------
__global__ void kscan(const float* __restrict__ Y){
    int gtid = blockIdx.x*blockDim.x + threadIdx.x;
    int bg   = gtid >> 16;
    int off4 = gtid & 65535;
    int b = bg / GG, g = bg % GG;
    const float4 y4 = reinterpret_cast<const float4*>(Y)[(size_t)(b*16 + g)*65536 + off4];
    int l = off4 * 4;
    int u = l >> 9, v = l & 511;
    float vals[4] = {y4.x, y4.y, y4.z, y4.w};
    #pragma unroll
    for (int r = 0; r < 4; ++r){
        if (vals[r] == 0.0f){
            int pos = atomicAdd(&g_znum[bg], 1);
            if (pos < ZCAP) g_zlist[bg*ZCAP + pos] = make_int2(u, v + r);
            atomicAdd(&g_zcnt[bg*512 + v + r], 1);
        }
    }
}

// -------- K1: per (b,f): Gram MMA -> T1/T2, fused Q MMA -> Qhi/Qlo + k0 --------
__global__ void __launch_bounds__(512, 1) k1_gram(const float* __restrict__ infos,
                                                  const float* __restrict__ Wd,
                                                  const float* __restrict__ bd,
                                                  const float* __restrict__ Wn){
    extern __shared__ __align__(16) char smc[];
    __shared__ float sT1[128], sT2[128], sVec[128];

    int bf = blockIdx.x, b = bf >> 4, f = bf & 15;
    int t = threadIdx.x, wid = t >> 5, lane = t & 31;
    int wm = wid & 3, wn = wid >> 2;
    int m0 = wm*32, n0 = wn*32;
    int g = lane >> 2, t4 = lane & 3;

    u32 sb = smem_u32(smc);
    u32 aBase  = sb + (u32)(((m0 + (lane & 15))*ST + (lane >> 4)*8) * 2);
    u32 bBase  = sb + (u32)(((n0 + (lane & 7) + ((lane >> 4) & 1)*8)*ST + ((lane >> 3) & 1)*8) * 2);
    u32 bBaseT = sb + (u32)(((lane & 15)*ST + n0 + (lane >> 4)*8) * 2);   // trans-B lane addr (tile-rel)

    if (t < 128){ sT1[t] = 0.0f; sT2[t] = 0.0f; }

    // ---- Gram: G[c][c'] = sum_u X[u,c] X[u,c'], K=512 in 4 chunks, reg-prefetched ----
    int cr = t >> 2, uh = (t & 3)*32;
    const float* xrow = infos + (((size_t)b*128 + cr)*16 + f)*512 + uh;
    float t2acc = 0.0f;
    float acc[2][4][4] = {};
    float4 pf[8];
    #pragma unroll
    for (int i = 0; i < 8; ++i) pf[i] = *reinterpret_cast<const float4*>(xrow + i*4);

    for (int kk = 0; kk < 4; ++kk){
        #pragma unroll
        for (int i = 0; i < 8; ++i){
            int ul = uh + i*4;
            t2acc += pf[i].x + pf[i].y + pf[i].z + pf[i].w;
            u64 hv, lv; pack4(pf[i], hv, lv);
            *reinterpret_cast<u64*>(smc + (cr*ST + ul)*2)         = hv;
            *reinterpret_cast<u64*>(smc + TILEB + (cr*ST + ul)*2) = lv;
        }
        __syncthreads();
        if (kk < 3){
            #pragma unroll
            for (int i = 0; i < 8; ++i) pf[i] = *reinterpret_cast<const float4*>(xrow + (kk+1)*128 + i*4);
        }
        gemm_tile(acc, aBase, aBase + TILEB, bBase, bBase + TILEB);
        __syncthreads();
    }
    atomicAdd(&sT2[cr], t2acc);
    __syncthreads();

    // ---- WS = W1+W3 fp32 [128][129] at smem offset 0 (X tiles dead) ----
    {
        float* sWS = reinterpret_cast<float*>(smc);
        int d = t >> 2, ch = (t & 3)*32;
        #pragma unroll
        for (int i = 0; i < 8; ++i){
            int c0 = ch + i*4;
            float4 a  = *reinterpret_cast<const float4*>(Wd + d*384 + c0);
            float4 c3 = *reinterpret_cast<const float4*>(Wd + d*384 + 256 + c0);
            sWS[d*129 + c0 + 0] = a.x + c3.x;
            sWS[d*129 + c0 + 1] = a.y + c3.y;
            sWS[d*129 + c0 + 2] = a.z + c3.z;
            sWS[d*129 + c0 + 3] = a.w + c3.w;
        }
    }
    __syncthreads();

    // ---- T1 epilogue straight from Gram accumulators ----
    {
        const float* sWS = reinterpret_cast<const float*>(smc);
        #pragma unroll
        for (int mi = 0; mi < 2; ++mi){
            int r0 = m0 + mi*16 + g, r1 = r0 + 8;
            float s0 = 0.0f, s1 = 0.0f;
            #pragma unroll
            for (int ni = 0; ni < 4; ++ni){
                int col = n0 + ni*8 + 2*t4;
                s0 += acc[mi][ni][0]*sWS[r0*129 + col] + acc[mi][ni][1]*sWS[r0*129 + col + 1];
                s1 += acc[mi][ni][2]*sWS[r1*129 + col] + acc[mi][ni][3]*sWS[r1*129 + col + 1];
            }
            atomicAdd(&sT1[r0], s0);
            atomicAdd(&sT1[r1], s1);
        }
    }
    __syncthreads();
    if (t < 128){
        float t1v = sT1[t], t2v = sT2[t];
        g_T1[bf*128 + t] = t1v;
        g_T2[bf*128 + t] = t2v;
        sVec[t] = t1v + t2v * bd[t];
    }
    __syncthreads();

    // ---- Wn tiles (hi@0, lo@TILEB), BQ tiles as [c][e] rows (hi@2T, lo@3T) ----
    {
        int o = t >> 2, ch = (t & 3)*32;
        #pragma unroll
        for (int i = 0; i < 8; ++i){
            int c0 = ch + i*4;
            float4 w = *reinterpret_cast<const float4*>(Wn + o*128 + c0);
            u64 hv, lv; pack4(w, hv, lv);
            *reinterpret_cast<u64*>(smc + (o*ST + c0)*2)         = hv;
            *reinterpret_cast<u64*>(smc + TILEB + (o*ST + c0)*2) = lv;
        }
    }
    {
        int c = t >> 2, eb = (t & 3)*32;
        float t2c = sT2[c];
        #pragma unroll
        for (int i = 0; i < 8; ++i){
            int e0 = eb + i*4;
            float4 a  = *reinterpret_cast<const float4*>(Wd + c*384 + 128 + e0);
            float4 c3 = *reinterpret_cast<const float4*>(Wd + c*384 + 256 + e0);
            float4 v4 = make_float4(t2c*(a.x - c3.x), t2c*(a.y - c3.y), t2c*(a.z - c3.z), t2c*(a.w - c3.w));
            u64 hv, lv; pack4(v4, hv, lv);
            *reinterpret_cast<u64*>(smc + 2*TILEB + (c*ST + e0)*2) = hv;
            *reinterpret_cast<u64*>(smc + 3*TILEB + (c*ST + e0)*2) = lv;
        }
    }
    __syncthreads();

    float qacc[2][4][4] = {};
    gemm_tile_tb(qacc, aBase, aBase + TILEB, bBaseT + 2*TILEB, bBaseT + 3*TILEB);

    // ---- Q epilogue: split to bf16 hi/lo, plain [o][e] rows in gmem ----
    #pragma unroll
    for (int mi = 0; mi < 2; ++mi){
        int r0 = m0 + mi*16 + g, r1 = r0 + 8;
        #pragma unroll
        for (int ni = 0; ni < 4; ++ni){
            int col = n0 + ni*8 + 2*t4;
            u16 h0,l0,h1,l1;
            bfsplit(qacc[mi][ni][0], h0, l0); bfsplit(qacc[mi][ni][1], h1, l1);
            g_Qh[bf*8192 + r0*64 + (col >> 1)] = (u32)h0 | ((u32)h1 << 16);
            g_Ql[bf*8192 + r0*64 + (col >> 1)] = (u32)l0 | ((u32)l1 << 16);
            bfsplit(qacc[mi][ni][2], h0, l0); bfsplit(qacc[mi][ni][3], h1, l1);
            g_Qh[bf*8192 + r1*64 + (col >> 1)] = (u32)h0 | ((u32)h1 << 16);
            g_Ql[bf*8192 + r1*64 + (col >> 1)] = (u32)l0 | ((u32)l1 << 16);
        }
    }

    // ---- k0[o] = sum_c Wn[o,c]*sVec[c] from smem Wn hi/lo tiles ----
    if (t < 128){
        float s = 0.0f;
        #pragma unroll 4
        for (int c2 = 0; c2 < 128; c2 += 2){
            u32 hw = *reinterpret_cast<const u32*>(smc + (t*ST + c2)*2);
            u32 lw = *reinterpret_cast<const u32*>(smc + TILEB + (t*ST + c2)*2);
            float w0 = bf2f(hw & 0xffff) + bf2f(lw & 0xffff);
            float w1 = bf2f(hw >> 16)    + bf2f(lw >> 16);
            s += w0*sVec[c2] + w1*sVec[c2 + 1];
        }
        g_k0[bf*128 + t] = s;
    }
}

// -------- K3: persistent per-bf CTA; out = relu(fma(Q@X, 1/512, k0/512 + bn)) --------
// A = Q [o][e] rows (hi@0, lo@TILEB); B = X [e][v] rows via ldmatrix.trans (hi@2T, lo@3T)
__global__ void __launch_bounds__(512, 1) k3_out(const float* __restrict__ infos,
                                                 const float* __restrict__ bn,
                                                 float* __restrict__ out){
    extern __shared__ __align__(16) char smc[];
    __shared__ float sBase[128];

    int bf = blockIdx.x;
    int b = bf >> 4, f = bf & 15;
    int t = threadIdx.x, wid = t >> 5, lane = t & 31;
    int wm = wid & 3, wn = wid >> 2;
    int m0 = wm*32, n0 = wn*32;
    int g = lane >> 2, t4 = lane & 3;

    u32 sb = smem_u32(smc);
    u32 aBase  = sb + (u32)(((m0 + (lane & 15))*ST + (lane >> 4)*8) * 2);
    u32 bBaseT = sb + 2*TILEB + (u32)(((lane & 15)*ST + n0 + (lane >> 4)*8) * 2);

    if (t < 128) sBase[t] = g_k0[bf*128 + t]*(1.0f/512.0f) + bn[t];

    // Q tiles: raw row copy (already bf16 [o][e])
    {
        const u64* qh = reinterpret_cast<const u64*>(g_Qh + bf*8192);
        const u64* ql = reinterpret_cast<const u64*>(g_Ql + bf*8192);
        for (int i = t; i < 4096; i += 512){
            int row = i >> 5, c8 = i & 31;
            *reinterpret_cast<u64*>(smc + row*ST*2 + c8*8)         = qh[i];
            *reinterpret_cast<u64*>(smc + TILEB + row*ST*2 + c8*8) = ql[i];
        }
    }

    // X fill mapping: row e = t>>2, v chunk (t&3)*32; coalesced row-major stores
    int e = t >> 2, vb = (t & 3)*32;
    const float* xr = infos + (((size_t)b*128 + e)*16 + f)*512 + vb;
    const float inv = 1.0f/512.0f;

    float4 pf[8];
    #pragma unroll
    for (int i = 0; i < 8; ++i) pf[i] = *reinterpret_cast<const float4*>(xr + i*4);

    for (int vt = 0; vt < 4; ++vt){
        // convert + store current X tile [e][v]
        #pragma unroll
        for (int i = 0; i < 8; ++i){
            int vl = vb + i*4;
            u64 hv, lv; pack4(pf[i], hv, lv);
            *reinterpret_cast<u64*>(smc + 2*TILEB + (e*ST + vl)*2) = hv;
            *reinterpret_cast<u64*>(smc + 3*TILEB + (e*ST + vl)*2) = lv;
        }
        __syncthreads();
        if (vt < 3){
            #pragma unroll
            for (int i = 0; i < 8; ++i) pf[i] = *reinterpret_cast<const float4*>(xr + (vt+1)*128 + i*4);
        }

        float acc[2][4][4] = {};
        gemm_tile_tb(acc, aBase, aBase + TILEB, bBaseT, bBaseT + TILEB);

        // epilogue: m = o, n = v (v-pairs contiguous -> STG.64)
        int v0 = vt*128;
        #pragma unroll
        for (int mi = 0; mi < 2; ++mi){
            int o0 = m0 + mi*16 + g, o1 = o0 + 8;
            size_t base0 = ((size_t)(b*128 + o0)*16 + f)*512 + v0;
            size_t base1 = ((size_t)(b*128 + o1)*16 + f)*512 + v0;
            #pragma unroll
            for (int ni = 0; ni < 4; ++ni){
                int vc = n0 + ni*8 + 2*t4;
                float2 r0, r1;
                r0.x = fmaxf(fmaf(acc[mi][ni][0], inv, sBase[o0]), 0.0f);
                r0.y = fmaxf(fmaf(acc[mi][ni][1], inv, sBase[o0]), 0.0f);
                r1.x = fmaxf(fmaf(acc[mi][ni][2], inv, sBase[o1]), 0.0f);
                r1.y = fmaxf(fmaf(acc[mi][ni][3], inv, sBase[o1]), 0.0f);
                *reinterpret_cast<float2*>(out + base0 + vc) = r0;
                *reinterpret_cast<float2*>(out + base1 + vc) = r1;
            }
        }
        __syncthreads();
    }
}

// -------- K4: exact recompute of the rare zero-affected output columns --------
__global__ void k4_fix(const float* __restrict__ infos, const float* __restrict__ Wd,
                       const float* __restrict__ bd, const float* __restrict__ Wn,
                       const float* __restrict__ bn, float* __restrict__ out){
    int slot = blockIdx.x;
    int bf   = blockIdx.y;
    int b = bf >> 4, f = bf & 15;
    int g = (f == 0) ? 0 : ((f <= 11) ? 1 : 2);
    int bg = b*GG + g;
    int nz = g_znum[bg]; if (nz > ZCAP) nz = ZCAP;
    int t = threadIdx.x;

    __shared__ float sXv[128];
    __shared__ float sXu[16][128];
    __shared__ float sAgg[128];
    __shared__ int   sUs[16];
    __shared__ int   sM;

    for (int i = slot; i < nz; i += 16){
        int vz = g_zlist[bg*ZCAP + i].y;
        bool dup = false;
        for (int jj = 0; jj < i; ++jj)
            if (g_zlist[bg*ZCAP + jj].y == vz){ dup = true; break; }
        if (dup) continue;

        if (t == 0){
            int m = 0;
            for (int jj = 0; jj < nz; ++jj){
                int2 e = g_zlist[bg*ZCAP + jj];
                if (e.y == vz && m < 16) sUs[m++] = e.x;
            }
            sM = m;
        }
        __syncthreads();
        int m = sM;

        sXv[t] = infos[(size_t)(b*2048 + t*16 + f)*512 + vz];
        for (int k = 0; k < m; ++k)
            sXu[k][t] = infos[(size_t)(b*2048 + t*16 + f)*512 + sUs[k]];
        __syncthreads();

        int c = t;
        float Dv = 0.0f;
        for (int e = 0; e < 128; ++e)
            Dv += sXv[e] * (Wd[c*384 + 128 + e] - Wd[c*384 + 256 + e]);
        float a1 = g_T1[bf*128 + c];
        float a2 = g_T2[bf*128 + c];
        for (int k = 0; k < m; ++k){
            float S = 0.0f;
            for (int e = 0; e < 128; ++e)
                S += sXu[k][e] * (Wd[c*384 + e] + Wd[c*384 + 256 + e]);
            a1 -= sXu[k][c] * S;
            a2 -= sXu[k][c];
        }
        int degi = 512 - g_zcnt[bg*512 + vz];
        float deg = (float)(degi > 1 ? degi : 1);
        sAgg[c] = (a1 + a2*(Dv + bd[c])) / deg;
        __syncthreads();

        float s = 0.0f;
        for (int cc = 0; cc < 128; ++cc) s += sAgg[cc] * Wn[t*128 + cc];
        s += bn[t];
        out[(size_t)(b*2048 + t*16 + f)*512 + vz] = fmaxf(s, 0.0f);
        __syncthreads();
    }
}

extern "C" void kernel_launch(void* const* d_in, const int* in_sizes, int n_in,
                              void* d_out, int out_size){
    const float* Y     = (const float*)d_in[0];
    const float* infos = (const float*)d_in[1];
    const float* Wd    = (const float*)d_in[2];
    const float* bd    = (const float*)d_in[3];
    const float* Wn    = (const float*)d_in[4];
    const float* bn    = (const float*)d_in[5];
    float* out = (float*)d_out;

    cudaFuncSetAttribute(k1_gram, cudaFuncAttributeMaxDynamicSharedMemorySize, DYNSM);
    cudaFuncSetAttribute(k3_out,  cudaFuncAttributeMaxDynamicSharedMemorySize, DYNSM);

    kinit<<<16, 256>>>();
    kscan<<<6144, 256>>>(Y);
    k1_gram<<<128, 512, DYNSM>>>(infos, Wd, bd, Wn);
    k3_out<<<128, 512, DYNSM>>>(infos, bn, out);
    k4_fix<<<dim3(16, 128), 128>>>(infos, Wd, bd, Wn, bn, out);
}

// round 9
// speedup vs baseline: 1.7261x; 1.0052x over previous
#include <cuda_runtime.h>
#include <cuda_bf16.h>
#include <cstdint>

typedef unsigned int u32;
typedef unsigned long long u64;
typedef unsigned short u16;

#define GG 3
#define ZCAP 4096
#define ST 136                 // bf16 elements per padded tile row (272 B)
#define TILEB (128*ST*2)       // 34816 bytes per 128x128 bf16 tile
#define DYNSM (6*TILEB)        // 208896

// ---------------- device scratch (allocation-free) ----------------
__device__ float g_T1[16384];
__device__ float g_T2[16384];
__device__ int   g_znum[24];
__device__ int   g_zcnt[24*512];
__device__ int2  g_zlist[24*ZCAP];

// ---------------- helpers ----------------
static __device__ __forceinline__ u32 smem_u32(const void* p){
    u32 a;
    asm("{ .reg .u64 t; cvta.to.shared.u64 t, %1; cvt.u32.u64 %0, t; }" : "=r"(a) : "l"(p));
    return a;
}
#define LDSM_X4(r, a) \
    asm volatile("ldmatrix.sync.aligned.m8n8.x4.shared.b16 {%0,%1,%2,%3}, [%4];" \
        : "=r"((r)[0]),"=r"((r)[1]),"=r"((r)[2]),"=r"((r)[3]) : "r"(a))
#define LDSM_X4_T(r, a) \
    asm volatile("ldmatrix.sync.aligned.m8n8.x4.trans.shared.b16 {%0,%1,%2,%3}, [%4];" \
        : "=r"((r)[0]),"=r"((r)[1]),"=r"((r)[2]),"=r"((r)[3]) : "r"(a))

static __device__ __forceinline__ void mma16816(float* c, const u32* a, const u32* b){
    asm volatile("mma.sync.aligned.m16n8k16.row.col.f32.bf16.bf16.f32 "
        "{%0,%1,%2,%3}, {%4,%5,%6,%7}, {%8,%9}, {%0,%1,%2,%3};"
        : "+f"(c[0]),"+f"(c[1]),"+f"(c[2]),"+f"(c[3])
        : "r"(a[0]),"r"(a[1]),"r"(a[2]),"r"(a[3]), "r"(b[0]),"r"(b[1]));
}
// truncation split of two floats: h = packed bf16 hi (exact truncation),
// l = packed bf16 of exact residuals. a -> low half, b -> high half.
static __device__ __forceinline__ void split2(float a, float b, u32& h, u32& l){
    u32 ua = __float_as_uint(a), ub = __float_as_uint(b);
    h = __byte_perm(ua, ub, 0x7632);
    float la = a - __uint_as_float(ua & 0xFFFF0000u);
    float lb = b - __uint_as_float(ub & 0xFFFF0000u);
    asm("cvt.rn.bf16x2.f32 %0, %1, %2;" : "=r"(l) : "f"(lb), "f"(la));
}
static __device__ __forceinline__ void pack4(float4 x, u64& hv, u64& lv){
    u32 h01, l01, h23, l23;
    split2(x.x, x.y, h01, l01);
    split2(x.z, x.w, h23, l23);
    hv = (u64)h01 | ((u64)h23 << 32);
    lv = (u64)l01 | ((u64)l23 << 32);
}
static __device__ __forceinline__ float bf2f(u32 bits16){ return __uint_as_float(bits16 << 16); }

// non-trans gemm (A [m][k] rows, B [n][k] rows), 3 split products, warp 32x32 tile
static __device__ __forceinline__ void gemm_tile(float acc[2][4][4], u32 aH, u32 aL, u32 bH, u32 bL){
    #pragma unroll
    for (int ks = 0; ks < 8; ++ks){
        u32 ah[2][4], al[2][4], bh[2][4], bl[2][4];
        #pragma unroll
        for (int mi = 0; mi < 2; ++mi){
            LDSM_X4(ah[mi], aH + mi*(16*ST*2) + ks*32);
            LDSM_X4(al[mi], aL + mi*(16*ST*2) + ks*32);
        }
        #pragma unroll
        for (int nj = 0; nj < 2; ++nj){
            LDSM_X4(bh[nj], bH + nj*(16*ST*2) + ks*32);
            LDSM_X4(bl[nj], bL + nj*(16*ST*2) + ks*32);
        }
        #pragma unroll
        for (int mi = 0; mi < 2; ++mi)
        #pragma unroll
        for (int nj = 0; nj < 2; ++nj){
            mma16816(acc[mi][nj*2],   ah[mi], &bh[nj][0]);
            mma16816(acc[mi][nj*2+1], ah[mi], &bh[nj][2]);
        }
        #pragma unroll
        for (int mi = 0; mi < 2; ++mi)
        #pragma unroll
        for (int nj = 0; nj < 2; ++nj){
            mma16816(acc[mi][nj*2],   ah[mi], &bl[nj][0]);
            mma16816(acc[mi][nj*2+1], ah[mi], &bl[nj][2]);
        }
        #pragma unroll
        for (int mi = 0; mi < 2; ++mi)
        #pragma unroll
        for (int nj = 0; nj < 2; ++nj){
            mma16816(acc[mi][nj*2],   al[mi], &bh[nj][0]);
            mma16816(acc[mi][nj*2+1], al[mi], &bh[nj][2]);
        }
    }
}

// trans-B gemm (A [m][k] rows, B [k][n] rows via ldmatrix.trans)
static __device__ __forceinline__ void gemm_tile_tb(float acc[2][4][4], u32 aH, u32 aL, u32 bH, u32 bL){
    #pragma unroll
    for (int ks = 0; ks < 8; ++ks){
        u32 ah[2][4], al[2][4], bh[2][4], bl[2][4];
        #pragma unroll
        for (int mi = 0; mi < 2; ++mi){
            LDSM_X4(ah[mi], aH + mi*(16*ST*2) + ks*32);
            LDSM_X4(al[mi], aL + mi*(16*ST*2) + ks*32);
        }
        #pragma unroll
        for (int nj = 0; nj < 2; ++nj){
            LDSM_X4_T(bh[nj], bH + nj*32 + ks*(16*ST*2));
            LDSM_X4_T(bl[nj], bL + nj*32 + ks*(16*ST*2));
        }
        #pragma unroll
        for (int mi = 0; mi < 2; ++mi)
        #pragma unroll
        for (int nj = 0; nj < 2; ++nj){
            mma16816(acc[mi][nj*2],   ah[mi], &bh[nj][0]);
            mma16816(acc[mi][nj*2+1], ah[mi], &bh[nj][2]);
        }
        #pragma unroll
        for (int mi = 0; mi < 2; ++mi)
        #pragma unroll
        for (int nj = 0; nj < 2; ++nj){
            mma16816(acc[mi][nj*2],   ah[mi], &bl[nj][0]);
            mma16816(acc[mi][nj*2+1], ah[mi], &bl[nj][2]);
        }
        #pragma unroll
        for (int mi = 0; mi < 2; ++mi)
        #pragma unroll
        for (int nj = 0; nj < 2; ++nj){
            mma16816(acc[mi][nj*2],   al[mi], &bh[nj][0]);
            mma16816(acc[mi][nj*2+1], al[mi], &bh[nj][2]);
        }
    }
}

// -------- init --------
__global__ void kinit(){
    int t = blockIdx.x*blockDim.x + threadIdx.x;
    if (t < 24) g_znum[t] = 0;
    for (int i = t; i < 24*512; i += 16*256) g_zcnt[i] = 0;
}

// -------- scan Y slices 0..2 for exact zeros --------
__global__ void kscan(const float* __restrict__ Y){
    int gtid = blockIdx.x*blockDim.x + threadIdx.x;
    int bg   = gtid >> 16;
    int off4 = gtid & 65535;
    int b = bg / GG, g = bg % GG;
    const float4 y4 = reinterpret_cast<const float4*>(Y)[(size_t)(b*16 + g)*65536 + off4];
    int l = off4 * 4;
    int u = l >> 9, v = l & 511;
    float vals[4] = {y4.x, y4.y, y4.z, y4.w};
    #pragma unroll
    for (int r = 0; r < 4; ++r){
        if (vals[r] == 0.0f){
            int pos = atomicAdd(&g_znum[bg], 1);
            if (pos < ZCAP) g_zlist[bg*ZCAP + pos] = make_int2(u, v + r);
            atomicAdd(&g_zcnt[bg*512 + v + r], 1);
        }
    }
}

// -------- fused kernel: Gram -> T1/T2 -> Q -> output, one CTA per (b,f) --------
__global__ void __launch_bounds__(512, 1) kfuse(const float* __restrict__ infos,
                                                const float* __restrict__ Wd,
                                                const float* __restrict__ bd,
                                                const float* __restrict__ Wn,
                                                const float* __restrict__ bn,
                                                float* __restrict__ out){
    extern __shared__ __align__(16) char smc[];
    __shared__ float sT1[128], sT2[128], sVec[128], sBase[128];

    int bf = blockIdx.x, b = bf >> 4, f = bf & 15;
    int t = threadIdx.x, wid = t >> 5, lane = t & 31;
    int wm = wid & 3, wn = wid >> 2;
    int m0 = wm*32, n0 = wn*32;
    int g = lane >> 2, t4 = lane & 3;

    u32 sb = smem_u32(smc);
    u32 aBase = sb + (u32)(((m0 + (lane & 15))*ST + (lane >> 4)*8) * 2);
    u32 bBase = sb + (u32)(((n0 + (lane & 7) + ((lane >> 4) & 1)*8)*ST + ((lane >> 3) & 1)*8) * 2);
    u32 bToff = (u32)(((lane & 15)*ST + n0 + (lane >> 4)*8) * 2);

    if (t < 128){ sT1[t] = 0.0f; sT2[t] = 0.0f; }

    // ---- WS = W1+W3 fp32 [128][129] at S4 (untouched during Gram) ----
    {
        float* sWS = reinterpret_cast<float*>(smc + 4*TILEB);
        int d = t >> 2, ch = (t & 3)*32;
        #pragma unroll
        for (int i = 0; i < 8; ++i){
            int c0 = ch + i*4;
            float4 a  = *reinterpret_cast<const float4*>(Wd + d*384 + c0);
            float4 c3 = *reinterpret_cast<const float4*>(Wd + d*384 + 256 + c0);
            sWS[d*129 + c0 + 0] = a.x + c3.x;
            sWS[d*129 + c0 + 1] = a.y + c3.y;
            sWS[d*129 + c0 + 2] = a.z + c3.z;
            sWS[d*129 + c0 + 3] = a.w + c3.w;
        }
    }

    // ---- Gram: G = X X^T, K=512 in 4 chunks, reg-prefetched (X hi@S0, lo@S1) ----
    int cr = t >> 2, uh = (t & 3)*32;
    const float* xrow = infos + (((size_t)b*128 + cr)*16 + f)*512 + uh;
    float t2acc = 0.0f;
    float acc[2][4][4] = {};
    float4 pf[8];
    #pragma unroll
    for (int i = 0; i < 8; ++i) pf[i] = *reinterpret_cast<const float4*>(xrow + i*4);

    for (int kk = 0; kk < 4; ++kk){
        #pragma unroll
        for (int i = 0; i < 8; ++i){
            int ul = uh + i*4;
            t2acc += pf[i].x + pf[i].y + pf[i].z + pf[i].w;
            u64 hv, lv; pack4(pf[i], hv, lv);
            *reinterpret_cast<u64*>(smc + (cr*ST + ul)*2)         = hv;
            *reinterpret_cast<u64*>(smc + TILEB + (cr*ST + ul)*2) = lv;
        }
        __syncthreads();
        if (kk < 3){
            #pragma unroll
            for (int i = 0; i < 8; ++i) pf[i] = *reinterpret_cast<const float4*>(xrow + (kk+1)*128 + i*4);
        }
        gemm_tile(acc, aBase, aBase + TILEB, bBase, bBase + TILEB);
        __syncthreads();
    }
    // NOTE: pf now holds chunk 3 == output v-tile 3
    atomicAdd(&sT2[cr], t2acc);
    __syncthreads();

    // ---- T1 epilogue from Gram accumulators (WS @ S4) ----
    {
        const float* sWS = reinterpret_cast<const float*>(smc + 4*TILEB);
        #pragma unroll
        for (int mi = 0; mi < 2; ++mi){
            int r0 = m0 + mi*16 + g, r1 = r0 + 8;
            float s0 = 0.0f, s1 = 0.0f;
            #pragma unroll
            for (int ni = 0; ni < 4; ++ni){
                int col = n0 + ni*8 + 2*t4;
                s0 += acc[mi][ni][0]*sWS[r0*129 + col] + acc[mi][ni][1]*sWS[r0*129 + col + 1];
                s1 += acc[mi][ni][2]*sWS[r1*129 + col] + acc[mi][ni][3]*sWS[r1*129 + col + 1];
            }
            atomicAdd(&sT1[r0], s0);
            atomicAdd(&sT1[r1], s1);
        }
    }
    __syncthreads();
    if (t < 128){
        float t1v = sT1[t], t2v = sT2[t];
        g_T1[bf*128 + t] = t1v;
        g_T2[bf*128 + t] = t2v;
        sVec[t] = t1v + t2v * bd[t];
    }
    __syncthreads();

    // ---- Wn tiles (hi@S0, lo@S1) + BQ [c][e] rows (hi@S2, lo@S3) ----
    {
        int o = t >> 2, ch = (t & 3)*32;
        #pragma unroll
        for (int i = 0; i < 8; ++i){
            int c0 = ch + i*4;
            float4 w = *reinterpret_cast<const float4*>(Wn + o*128 + c0);
            u64 hv, lv; pack4(w, hv, lv);
            *reinterpret_cast<u64*>(smc + (o*ST + c0)*2)         = hv;
            *reinterpret_cast<u64*>(smc + TILEB + (o*ST + c0)*2) = lv;
        }
    }
    {
        int c = t >> 2, eb = (t & 3)*32;
        float t2c = sT2[c];
        #pragma unroll
        for (int i = 0; i < 8; ++i){
            int e0 = eb + i*4;
            float4 a  = *reinterpret_cast<const float4*>(Wd + c*384 + 128 + e0);
            float4 c3 = *reinterpret_cast<const float4*>(Wd + c*384 + 256 + e0);
            float4 v4 = make_float4(t2c*(a.x - c3.x), t2c*(a.y - c3.y), t2c*(a.z - c3.z), t2c*(a.w - c3.w));
            u64 hv, lv; pack4(v4, hv, lv);
            *reinterpret_cast<u64*>(smc + 2*TILEB + (c*ST + e0)*2) = hv;
            *reinterpret_cast<u64*>(smc + 3*TILEB + (c*ST + e0)*2) = lv;
        }
    }
    __syncthreads();

    // ---- k0[o] (t<128, from Wn smem) then Q gemm (all warps) ----
    float ksum = 0.0f;
    if (t < 128){
        #pragma unroll 4
        for (int c2 = 0; c2 < 128; c2 += 2){
            u32 hw = *reinterpret_cast<const u32*>(smc + (t*ST + c2)*2);
            u32 lw = *reinterpret_cast<const u32*>(smc + TILEB + (t*ST + c2)*2);
            float w0 = bf2f(hw & 0xffff) + bf2f(lw & 0xffff);
            float w1 = bf2f(hw >> 16)    + bf2f(lw >> 16);
            ksum += w0*sVec[c2] + w1*sVec[c2 + 1];
        }
    }
    float qacc[2][4][4] = {};
    gemm_tile_tb(qacc, aBase, aBase + TILEB, sb + 2*TILEB + bToff, sb + 3*TILEB + bToff);
    __syncthreads();

    // ---- Q epilogue: split to bf16 hi/lo straight into S0/S1 (overwrite Wn) ----
    #pragma unroll
    for (int mi = 0; mi < 2; ++mi){
        int r0 = m0 + mi*16 + g, r1 = r0 + 8;
        #pragma unroll
        for (int ni = 0; ni < 4; ++ni){
            int col = n0 + ni*8 + 2*t4;
            u32 h01, l01;
            split2(qacc[mi][ni][0], qacc[mi][ni][1], h01, l01);
            *reinterpret_cast<u32*>(smc + (r0*ST + col)*2)         = h01;
            *reinterpret_cast<u32*>(smc + TILEB + (r0*ST + col)*2) = l01;
            split2(qacc[mi][ni][2], qacc[mi][ni][3], h01, l01);
            *reinterpret_cast<u32*>(smc + (r1*ST + col)*2)         = h01;
            *reinterpret_cast<u32*>(smc + TILEB + (r1*ST + col)*2) = l01;
        }
    }
    if (t < 128) sBase[t] = ksum*(1.0f/512.0f) + bn[t];

    // ---- fill buf0 (S2/S3) with v-tile 3 (pf already holds it); prefetch vt0 ----
    {
        #pragma unroll
        for (int i = 0; i < 8; ++i){
            int vl = uh + i*4;
            u64 hv, lv; pack4(pf[i], hv, lv);
            *reinterpret_cast<u64*>(smc + 2*TILEB + (cr*ST + vl)*2) = hv;
            *reinterpret_cast<u64*>(smc + 3*TILEB + (cr*ST + vl)*2) = lv;
        }
        #pragma unroll
        for (int i = 0; i < 8; ++i) pf[i] = *reinterpret_cast<const float4*>(xrow + i*4);   // vt0
    }
    __syncthreads();

    // ---- output loop, tile order {3,0,1,2}, double-buffered S2/S3 <-> S4/S5 ----
    const float inv = 1.0f/512.0f;
    #pragma unroll
    for (int it = 0; it < 4; ++it){
        const int ord[4] = {3,0,1,2};
        int vt = ord[it];
        u32 curB = sb + (2 + 2*(it & 1))*TILEB + bToff;
        u32 othW = (2 + 2*((it + 1) & 1))*TILEB;
        if (it < 3){
            #pragma unroll
            for (int i = 0; i < 8; ++i){
                int vl = uh + i*4;
                u64 hv, lv; pack4(pf[i], hv, lv);
                *reinterpret_cast<u64*>(smc + othW + (cr*ST + vl)*2)         = hv;
                *reinterpret_cast<u64*>(smc + othW + TILEB + (cr*ST + vl)*2) = lv;
            }
            if (it < 2){
                #pragma unroll
                for (int i = 0; i < 8; ++i) pf[i] = *reinterpret_cast<const float4*>(xrow + ord[it+2]*128 + i*4);
            }
        }

        float acc2[2][4][4] = {};
        gemm_tile_tb(acc2, aBase, aBase + TILEB, curB, curB + TILEB);

        int v0 = vt*128;
        #pragma unroll
        for (int mi = 0; mi < 2; ++mi){
            int o0 = m0 + mi*16 + g, o1 = o0 + 8;
            size_t base0 = ((size_t)(b*128 + o0)*16 + f)*512 + v0;
            size_t base1 = ((size_t)(b*128 + o1)*16 + f)*512 + v0;
            #pragma unroll
            for (int ni = 0; ni < 4; ++ni){
                int vc = n0 + ni*8 + 2*t4;
                float2 r0v, r1v;
                r0v.x = fmaxf(fmaf(acc2[mi][ni][0], inv, sBase[o0]), 0.0f);
                r0v.y = fmaxf(fmaf(acc2[mi][ni][1], inv, sBase[o0]), 0.0f);
                r1v.x = fmaxf(fmaf(acc2[mi][ni][2], inv, sBase[o1]), 0.0f);
                r1v.y = fmaxf(fmaf(acc2[mi][ni][3], inv, sBase[o1]), 0.0f);
                *reinterpret_cast<float2*>(out + base0 + vc) = r0v;
                *reinterpret_cast<float2*>(out + base1 + vc) = r1v;
            }
        }
        __syncthreads();
    }
}

// -------- K4: exact recompute of the rare zero-affected output columns --------
__global__ void k4_fix(const float* __restrict__ infos, const float* __restrict__ Wd,
                       const float* __restrict__ bd, const float* __restrict__ Wn,
                       const float* __restrict__ bn, float* __restrict__ out){
    int slot = blockIdx.x;
    int bf   = blockIdx.y;
    int b = bf >> 4, f = bf & 15;
    int g = (f == 0) ? 0 : ((f <= 11) ? 1 : 2);
    int bg = b*GG + g;
    int nz = g_znum[bg]; if (nz > ZCAP) nz = ZCAP;
    int t = threadIdx.x;

    __shared__ float sXv[128];
    __shared__ float sXu[16][128];
    __shared__ float sAgg[128];
    __shared__ int   sUs[16];
    __shared__ int   sM;

    for (int i = slot; i < nz; i += 16){
        int vz = g_zlist[bg*ZCAP + i].y;
        bool dup = false;
        for (int jj = 0; jj < i; ++jj)
            if (g_zlist[bg*ZCAP + jj].y == vz){ dup = true; break; }
        if (dup) continue;

        if (t == 0){
            int m = 0;
            for (int jj = 0; jj < nz; ++jj){
                int2 e = g_zlist[bg*ZCAP + jj];
                if (e.y == vz && m < 16) sUs[m++] = e.x;
            }
            sM = m;
        }
        __syncthreads();
        int m = sM;

        sXv[t] = infos[(size_t)(b*2048 + t*16 + f)*512 + vz];
        for (int k = 0; k < m; ++k)
            sXu[k][t] = infos[(size_t)(b*2048 + t*16 + f)*512 + sUs[k]];
        __syncthreads();

        int c = t;
        float Dv = 0.0f;
        for (int e = 0; e < 128; ++e)
            Dv += sXv[e] * (Wd[c*384 + 128 + e] - Wd[c*384 + 256 + e]);
        float a1 = g_T1[bf*128 + c];
        float a2 = g_T2[bf*128 + c];
        for (int k = 0; k < m; ++k){
            float S = 0.0f;
            for (int e = 0; e < 128; ++e)
                S += sXu[k][e] * (Wd[c*384 + e] + Wd[c*384 + 256 + e]);
            a1 -= sXu[k][c] * S;
            a2 -= sXu[k][c];
        }
        int degi = 512 - g_zcnt[bg*512 + vz];
        float deg = (float)(degi > 1 ? degi : 1);
        sAgg[c] = (a1 + a2*(Dv + bd[c])) / deg;
        __syncthreads();

        float s = 0.0f;
        for (int cc = 0; cc < 128; ++cc) s += sAgg[cc] * Wn[t*128 + cc];
        s += bn[t];
        out[(size_t)(b*2048 + t*16 + f)*512 + vz] = fmaxf(s, 0.0f);
        __syncthreads();
    }
}

extern "C" void kernel_launch(void* const* d_in, const int* in_sizes, int n_in,
                              void* d_out, int out_size){
    const float* Y     = (const float*)d_in[0];
    const float* infos = (const float*)d_in[1];
    const float* Wd    = (const float*)d_in[2];
    const float* bd    = (const float*)d_in[3];
    const float* Wn    = (const float*)d_in[4];
    const float* bn    = (const float*)d_in[5];
    float* out = (float*)d_out;

    cudaFuncSetAttribute(kfuse, cudaFuncAttributeMaxDynamicSharedMemorySize, DYNSM);

    kinit<<<16, 256>>>();
    kscan<<<6144, 256>>>(Y);
    kfuse<<<128, 512, DYNSM>>>(infos, Wd, bd, Wn, bn, out);
    k4_fix<<<dim3(16, 128), 128>>>(infos, Wd, bd, Wn, bn, out);
}